// round 2
// baseline (speedup 1.0000x reference)
#include <cuda_runtime.h>
#include <math.h>

// ---------------- problem constants ----------------
#define N_SW   131
#define NC2    (N_SW*N_SW)        // 17161
#define NLC    33                 // distinct |L-32| classes 0..32
#define NM     16                 // only m<16 are nonzero
#define BATCH  128
#define NV1    49                 // injection switches [0,49)
#define ROWS   (BATCH*NLC*NM)     // 67584 independent 131-dim complex systems

// ---------------- step-kernel tiling ----------------
#define TPB    512
#define WARPS  16
#define RPW    4                  // rows per warp
#define RPB    (WARPS*RPW)        // 64 rows per block
#define NBLK   (ROWS/RPB)         // 1056 (exact)
#define NSLOT  5                  // ceil(131/32) t-columns per lane

// dynamic smem layout
#define C_BYTES    (NC2*8)                    // 137288: C[s][t] as float2
#define OUT_OFF    C_BYTES
#define OUT_BYTES  (WARPS*RPW*N_SW*8)         // 67072: per-warp out rows
#define GAIN_OFF   (OUT_OFF+OUT_BYTES)        // 204360
#define SMEM_BYTES (GAIN_OFF + 544)           // 204904

// ---------------- persistent device scratch (no allocs allowed) ----------------
__device__ float2 g_field[(size_t)ROWS * N_SW];   // ~70.8 MB, rewritten fully every run
__device__ float2 g_C[NC2];                       // conn * e^{i*phase[t]}
__device__ float  g_gain[N_SW];                   // softplus(switch_gain)
__device__ float  g_pinj[BATCH * NM * NV1];       // 0.3/enc_max * p[b,s,m]
__device__ float  g_erow[10 * ROWS];              // per-row energy, final step
__device__ int    g_absmax_bits;

// ---------------- packed f32x2 helpers ----------------
__device__ __forceinline__ unsigned long long pack2(float x, float y) {
    unsigned long long r;
    asm("mov.b64 %0, {%1,%2};" : "=l"(r) : "f"(x), "f"(y));
    return r;
}
__device__ __forceinline__ void unpack2(unsigned long long v, float& x, float& y) {
    asm("mov.b64 {%0,%1}, %2;" : "=f"(x), "=f"(y) : "l"(v));
}
#define FMA2(acc, a, b) asm("fma.rn.f32x2 %0, %1, %2, %0;" : "+l"(acc) : "l"(a), "l"(b))

// ---------------- prep kernels ----------------
__global__ void k_init() {
    if (threadIdx.x == 0) g_absmax_bits = 0;
}

__global__ void k_absmax(const float* __restrict__ img, int n) {
    int i = blockIdx.x * blockDim.x + threadIdx.x;
    float v = (i < n) ? fabsf(img[i]) : 0.f;
    #pragma unroll
    for (int o = 16; o > 0; o >>= 1) v = fmaxf(v, __shfl_xor_sync(0xffffffffu, v, o));
    if ((threadIdx.x & 31) == 0) atomicMax(&g_absmax_bits, __float_as_int(v));
}

__global__ void k_prep(const float* __restrict__ cr, const float* __restrict__ ci,
                       const float* __restrict__ ph, const float* __restrict__ sg) {
    int i = blockIdx.x * blockDim.x + threadIdx.x;
    if (i < NC2) {
        int t = i % N_SW;
        float sp, cp;
        sincosf(ph[t], &sp, &cp);
        float a = cr[i], b = ci[i];
        g_C[i] = make_float2(a * cp - b * sp, a * sp + b * cp);  // conn * e^{i phase[t]}
    }
    if (i < N_SW) {
        float x = sg[i];                                          // softplus, stable
        g_gain[i] = fmaxf(x, 0.f) + log1pf(expf(-fabsf(x)));
    }
}

__global__ void k_pinj(const float* __restrict__ img) {
    int i = blockIdx.x * blockDim.x + threadIdx.x;
    if (i >= BATCH * NM * NV1) return;
    int b   = i / (NM * NV1);
    int rem = i - b * (NM * NV1);
    int m   = rem / NV1;
    int s   = rem - m * NV1;
    int pr = s / 7, pc = s - pr * 7;
    int ir = m >> 2, ic = m & 3;
    float am   = __int_as_float(g_absmax_bits);
    float coef = (am > 1e-8f) ? 0.3f / am : 0.3f;
    g_pinj[i] = coef * img[b * 784 + (pr * 4 + ir) * 28 + (pc * 4 + ic)];
}

// ---------------- main recurrence step ----------------
__global__ __launch_bounds__(TPB) void k_step(int step,
                                              const int* __restrict__ nsp,
                                              const int* __restrict__ injp) {
    extern __shared__ unsigned char smem[];
    float2* Csh     = (float2*)(smem);
    float2* out_sh  = (float2*)(smem + OUT_OFF);
    float*  gain_sh = (float*)(smem + GAIN_OFF);

    const int ns = *nsp;
    if (step >= ns) return;
    const int injs = *injp;

    for (int i = threadIdx.x; i < NC2; i += TPB) Csh[i] = g_C[i];
    for (int i = threadIdx.x; i < N_SW; i += TPB) gain_sh[i] = g_gain[i];
    __syncthreads();

    const int warp = threadIdx.x >> 5;
    const int lane = threadIdx.x & 31;
    const int rowBase = blockIdx.x * RPB + warp * RPW;
    float2* outw = out_sh + (size_t)warp * RPW * N_SW;

    unsigned long long acc[RPW][NSLOT];
    #pragma unroll
    for (int r = 0; r < RPW; r++)
        #pragma unroll
        for (int j = 0; j < NSLOT; j++) acc[r][j] = 0ull;

    if (step > 0) {
        // Phase A: recompute out_{t-1} = field * tanh(|f|*g)/(|f|+eps) from stored field
        #pragma unroll
        for (int r = 0; r < RPW; r++) {
            const float2* f = g_field + (size_t)(rowBase + r) * N_SW;
            #pragma unroll
            for (int j = 0; j < NSLOT; j++) {
                int t = lane + 32 * j;
                if (t < N_SW) {
                    float2 fv = f[t];
                    float mag = sqrtf(fv.x * fv.x + fv.y * fv.y + 1e-8f);
                    float sc  = tanhf(mag * gain_sh[t]) / (mag + 1e-8f);
                    outw[r * N_SW + t] = make_float2(fv.x * sc, fv.y * sc);
                }
            }
        }
        __syncwarp();

        // Phase B: g[t] = sum_s out[s] * C[s][t]  (complex), packed f32x2 FMAs
        const unsigned long long* C64 = (const unsigned long long*)Csh;
        const unsigned long long* O64 = (const unsigned long long*)outw;
        for (int s = 0; s < N_SW; s++) {
            unsigned long long b1[NSLOT], b2[NSLOT];
            #pragma unroll
            for (int j = 0; j < NSLOT; j++) {
                unsigned long long c = C64[s * N_SW + lane + 32 * j];  // j=4 tail: in-smem, unused
                float cr, ci;
                unpack2(c, cr, ci);
                b1[j] = c;
                b2[j] = pack2(-ci, cr);
            }
            #pragma unroll
            for (int r = 0; r < RPW; r++) {
                float orr, oii;
                unpack2(O64[r * N_SW + s], orr, oii);
                unsigned long long a1 = pack2(orr, orr);
                unsigned long long a2 = pack2(oii, oii);
                #pragma unroll
                for (int j = 0; j < NSLOT; j++) {
                    FMA2(acc[r][j], a1, b1[j]);   // (gr += or*Cr, gi += or*Ci)
                    FMA2(acc[r][j], a2, b2[j]);   // (gr -= oi*Ci, gi += oi*Cr)
                }
            }
        }
    }

    // Phase C: field = (field + inj)*0.85 + g*0.25 ; final step -> per-row energy
    const bool inject = (step < injs);
    const bool last   = (step == ns - 1);
    #pragma unroll
    for (int r = 0; r < RPW; r++) {
        int grow = rowBase + r;
        int b    = grow / (NLC * NM);
        int rem  = grow - b * (NLC * NM);
        int lc   = rem / NM;
        int m    = rem - lc * NM;
        float w    = 1.0f - (float)lc * 0.015625f;                  // 1 - d/64
        float mult = (lc == 0 || lc == NLC - 1) ? 1.0f : 2.0f;
        float2* f = g_field + (size_t)grow * N_SW;
        const float* pj = g_pinj + (b * NM + m) * NV1;
        #pragma unroll
        for (int j = 0; j < NSLOT; j++) {
            int t = lane + 32 * j;
            if (t >= N_SW) continue;
            float fr = 0.f, fi = 0.f;
            if (step > 0) { float2 fv = f[t]; fr = fv.x; fi = fv.y; }
            if (inject && t < NV1) fr += pj[t] * w;
            float gr, gi;
            unpack2(acc[r][j], gr, gi);
            fr = fr * 0.85f + gr * 0.25f;
            fi = fi * 0.85f + gi * 0.25f;
            f[t] = make_float2(fr, fi);
            if (last && t >= 121) {
                float mag = sqrtf(fr * fr + fi * fi + 1e-8f);
                float sc  = tanhf(mag * gain_sh[t]) / (mag + 1e-8f);
                float orr = fr * sc, oii = fi * sc;
                g_erow[(t - 121) * ROWS + grow] = mult * (orr * orr + oii * oii);
            }
        }
    }
}

// ---------------- readout ----------------
__global__ void k_final(const float* __restrict__ rw, const float* __restrict__ rb,
                        float* __restrict__ out) {
    __shared__ float feat[10];
    int b = blockIdx.x;
    int warp = threadIdx.x >> 5, lane = threadIdx.x & 31;
    if (warp < 10) {
        float s = 0.f;
        const float* e = g_erow + warp * ROWS + b * (NLC * NM);
        for (int k = lane; k < NLC * NM; k += 32) s += e[k];
        #pragma unroll
        for (int o = 16; o > 0; o >>= 1) s += __shfl_xor_sync(0xffffffffu, s, o);
        if (lane == 0) feat[warp] = log1pf(s + 1e-8f);
    }
    __syncthreads();
    if (threadIdx.x < 10) {
        int c = threadIdx.x;
        float acc = rb[c];
        #pragma unroll
        for (int o = 0; o < 10; o++) acc += feat[o] * rw[c * 10 + o];
        out[b * 10 + c] = acc;
    }
}

// ---------------- entry ----------------
extern "C" void kernel_launch(void* const* d_in, const int* in_sizes, int n_in,
                              void* d_out, int out_size) {
    const float* images = (const float*)d_in[0];
    const float* conn_r = (const float*)d_in[1];
    const float* conn_i = (const float*)d_in[2];
    const float* ph     = (const float*)d_in[3];
    const float* sg     = (const float*)d_in[4];
    const float* rw     = (const float*)d_in[5];
    const float* rb     = (const float*)d_in[6];
    const int*   nsp    = (const int*)d_in[7];
    const int*   injp   = (const int*)d_in[8];

    cudaFuncSetAttribute(k_step, cudaFuncAttributeMaxDynamicSharedMemorySize, SMEM_BYTES);

    k_init<<<1, 32>>>();
    const int n_img = BATCH * 28 * 28;
    k_absmax<<<(n_img + 511) / 512, 512>>>(images, n_img);
    k_prep<<<(NC2 + 255) / 256, 256>>>(conn_r, conn_i, ph, sg);
    k_pinj<<<(BATCH * NM * NV1 + 255) / 256, 256>>>(images);

    for (int t = 0; t < 10; t++)
        k_step<<<NBLK, TPB, SMEM_BYTES>>>(t, nsp, injp);

    k_final<<<BATCH, 320>>>(rw, rb, (float*)d_out);
}

// round 4
// speedup vs baseline: 1.4270x; 1.4270x over previous
#include <cuda_runtime.h>
#include <math.h>

// ---------------- problem constants ----------------
#define N_SW   131
#define NC2    (N_SW*N_SW)        // 17161
#define NLC    33                 // distinct |L-32| classes 0..32
#define NM     16                 // only m<16 are nonzero
#define BATCH  128
#define NV1    49                 // injection switches [0,49)
#define ROWS   (BATCH*NLC*NM)     // 67584 independent 131-dim complex systems

// ---------------- step-kernel tiling ----------------
#define TPB    256
#define WARPS  8
#define RPW    6                  // rows per warp
#define RPB    (WARPS*RPW)        // 48 rows per tile
#define NTILE  (ROWS/RPB)         // 1408 (exact)
#define GRID   148                // persistent: one CTA per SM

// dynamic smem layout (bytes)
#define C_BYTES    (NC2*8)                    // 137288: C[s][t] as (Cr,Ci) u64
#define OUT_OFF    C_BYTES
#define OUT_BYTES  (WARPS*RPW*N_SW*8)         // 50304: per-warp out rows (packed u64)
#define GAIN_OFF   (OUT_OFF+OUT_BYTES)
#define GAIN_BYTES 544
#define TAIL_OFF   (GAIN_OFF+GAIN_BYTES)
#define TAIL_BYTES (WARPS*RPW*3*8)            // 1152: per-warp tail g (t=128..130) float2
#define SMEM_BYTES (TAIL_OFF+TAIL_BYTES)      // ~189 KB

// ---------------- persistent device scratch (no allocs allowed) ----------------
__device__ float2 g_field[(size_t)ROWS * N_SW];   // ~70.8 MB state
__device__ float2 g_C[NC2];                       // conn * e^{i*phase[t]}
__device__ float  g_gain[N_SW];                   // softplus(switch_gain)
__device__ float  g_pinj[BATCH * NM * NV1];       // 0.3/enc_max * p[b,s,m]
__device__ float  g_erow[10 * ROWS];              // per-row energy, final step
__device__ int    g_absmax_bits;

// ---------------- packed f32x2 helpers ----------------
typedef unsigned long long u64;
__device__ __forceinline__ u64 pack2(float x, float y) {
    u64 r; asm("mov.b64 %0, {%1,%2};" : "=l"(r) : "f"(x), "f"(y)); return r;
}
__device__ __forceinline__ void unpack2(u64 v, float& x, float& y) {
    asm("mov.b64 {%0,%1}, %2;" : "=f"(x), "=f"(y) : "l"(v));
}
#define FMA2(acc, a, b) asm("fma.rn.f32x2 %0, %1, %2, %0;" : "+l"(acc) : "l"(a), "l"(b))

// fast tanh via MUFU ex2 (clamped; ~1e-6 rel err)
__device__ __forceinline__ float fast_tanh(float x) {
    float xc = fminf(x, 15.f);
    float e = __expf(2.f * xc);
    return __fdividef(e - 1.f, e + 1.f);
}

// ---------------- prep kernels ----------------
__global__ void k_init() { if (threadIdx.x == 0) g_absmax_bits = 0; }

__global__ void k_absmax(const float* __restrict__ img, int n) {
    int i = blockIdx.x * blockDim.x + threadIdx.x;
    float v = (i < n) ? fabsf(img[i]) : 0.f;
    #pragma unroll
    for (int o = 16; o > 0; o >>= 1) v = fmaxf(v, __shfl_xor_sync(0xffffffffu, v, o));
    if ((threadIdx.x & 31) == 0) atomicMax(&g_absmax_bits, __float_as_int(v));
}

__global__ void k_prep(const float* __restrict__ cr, const float* __restrict__ ci,
                       const float* __restrict__ ph, const float* __restrict__ sg) {
    int i = blockIdx.x * blockDim.x + threadIdx.x;
    if (i < NC2) {
        int t = i % N_SW;
        float sp, cp;
        sincosf(ph[t], &sp, &cp);
        float a = cr[i], b = ci[i];
        g_C[i] = make_float2(a * cp - b * sp, a * sp + b * cp);
    }
    if (i < N_SW) {
        float x = sg[i];
        g_gain[i] = fmaxf(x, 0.f) + log1pf(expf(-fabsf(x)));   // stable softplus
    }
}

__global__ void k_pinj(const float* __restrict__ img) {
    int i = blockIdx.x * blockDim.x + threadIdx.x;
    if (i >= BATCH * NM * NV1) return;
    int b   = i / (NM * NV1);
    int rem = i - b * (NM * NV1);
    int m   = rem / NV1;
    int s   = rem - m * NV1;
    int pr = s / 7, pc = s - pr * 7;
    int ir = m >> 2, ic = m & 3;
    float am   = __int_as_float(g_absmax_bits);
    float coef = (am > 1e-8f) ? 0.3f / am : 0.3f;
    g_pinj[i] = coef * img[b * 784 + (pr * 4 + ir) * 28 + (pc * 4 + ic)];
}

// ---------------- main recurrence step (persistent) ----------------
__global__ __launch_bounds__(TPB, 1) void k_step(int step,
                                                 const int* __restrict__ nsp,
                                                 const int* __restrict__ injp) {
    extern __shared__ unsigned char smem[];
    u64*    Csh     = (u64*)(smem);
    u64*    out_sh  = (u64*)(smem + OUT_OFF);
    float*  gain_sh = (float*)(smem + GAIN_OFF);
    float2* tail_sh = (float2*)(smem + TAIL_OFF);

    const int ns = *nsp;
    if (step >= ns) return;
    const int injs = *injp;
    const bool inject = (step < injs);
    const bool last   = (step == ns - 1);

    // load C + gain once per CTA
    {
        const u64* Cg = (const u64*)g_C;
        for (int i = threadIdx.x; i < NC2; i += TPB) Csh[i] = Cg[i];
        for (int i = threadIdx.x; i < N_SW; i += TPB) gain_sh[i] = g_gain[i];
    }
    __syncthreads();

    const int warp = threadIdx.x >> 5;
    const int lane = threadIdx.x & 31;
    u64*    outw = out_sh  + (size_t)warp * RPW * N_SW;
    float2* gt   = tail_sh + (size_t)warp * RPW * 3;

    // tail mapping: lane -> (row r_t = lane/4, t-index tx = lane%4)
    // lanes with r_t >= RPW or tx == 3 are dud lanes: they must still execute
    // the FMAs (uniform control flow) but read a CLAMPED, in-bounds address
    // and never write back.
    const int  r_t    = lane >> 2;
    const int  tx     = lane & 3;
    const bool tvalid = (tx < 3) && (r_t < RPW);
    const int  r_tc   = (r_t < RPW) ? r_t : 0;       // SAFE row for reads
    const int  txc    = (tx  < 3)  ? tx  : 2;        // SAFE col for reads

    for (int tile = blockIdx.x; tile < NTILE; tile += GRID) {
        const int rowBase = tile * RPB + warp * RPW;

        u64 acc1[RPW][4], acc2[RPW][4];
        #pragma unroll
        for (int r = 0; r < RPW; r++)
            #pragma unroll
            for (int j = 0; j < 4; j++) { acc1[r][j] = 0ull; acc2[r][j] = 0ull; }
        u64 ta1 = 0ull, ta2 = 0ull;

        if (step > 0) {
            // ---- Phase A: out = field * tanh(|f|*g)/(|f|+eps), packed into smem ----
            #pragma unroll
            for (int r = 0; r < RPW; r++) {
                const float2* f = g_field + (size_t)(rowBase + r) * N_SW;
                #pragma unroll
                for (int j = 0; j < 5; j++) {
                    int t = lane + 32 * j;
                    if (t < N_SW) {
                        float2 fv = f[t];
                        float sq  = fv.x * fv.x + fv.y * fv.y + 1e-8f;
                        float inv = rsqrtf(sq);
                        float mag = sq * inv;                 // sqrt(sq)
                        float th  = fast_tanh(mag * gain_sh[t]);
                        float sc  = __fdividef(th, mag + 1e-8f);
                        outw[r * N_SW + t] = pack2(fv.x * sc, fv.y * sc);
                    }
                }
            }
            __syncwarp();

            // ---- Phase B: g[t] = sum_s out[s] * C[s][t], split accumulators ----
            // acc1 += (or,or)*(Cr,Ci);  acc2 += (oi,oi)*(Cr,Ci)
            // gr = acc1.lo - acc2.hi;   gi = acc1.hi + acc2.lo
            const u64* Ot = outw + (size_t)r_tc * N_SW;   // clamped tail row (in-bounds)
            for (int s = 0; s < N_SW; s++) {
                const u64* Crow = Csh + s * N_SW;
                u64 c0 = Crow[lane];
                u64 c1 = Crow[lane + 32];
                u64 c2 = Crow[lane + 64];
                u64 c3 = Crow[lane + 96];
                // tail columns t=128..130 (lane-partitioned, 1 row x 1 col per lane)
                {
                    float orr, oii;
                    unpack2(Ot[s], orr, oii);
                    u64 a1 = pack2(orr, orr);
                    u64 a2 = pack2(oii, oii);
                    u64 ct = Crow[128 + txc];
                    FMA2(ta1, a1, ct);
                    FMA2(ta2, a2, ct);
                }
                #pragma unroll
                for (int r = 0; r < RPW; r++) {
                    float orr, oii;
                    unpack2(outw[r * N_SW + s], orr, oii);
                    u64 a1 = pack2(orr, orr);
                    u64 a2 = pack2(oii, oii);
                    FMA2(acc1[r][0], a1, c0);
                    FMA2(acc2[r][0], a2, c0);
                    FMA2(acc1[r][1], a1, c1);
                    FMA2(acc2[r][1], a2, c1);
                    FMA2(acc1[r][2], a1, c2);
                    FMA2(acc2[r][2], a2, c2);
                    FMA2(acc1[r][3], a1, c3);
                    FMA2(acc2[r][3], a2, c3);
                }
            }
            // tail writeback (only valid lanes write)
            {
                float t1x, t1y, t2x, t2y;
                unpack2(ta1, t1x, t1y);
                unpack2(ta2, t2x, t2y);
                if (tvalid) gt[r_t * 3 + tx] = make_float2(t1x - t2y, t1y + t2x);
            }
            __syncwarp();
        }

        // ---- Phase C: field = field*0.85 + inj*w*0.85 + g*0.25; last -> energy ----
        #pragma unroll
        for (int r = 0; r < RPW; r++) {
            int grow = rowBase + r;
            int b    = grow / (NLC * NM);
            int rem  = grow - b * (NLC * NM);
            int lc   = rem >> 4;
            int m    = rem & 15;
            float w    = 1.0f - (float)lc * 0.015625f;             // 1 - d/64
            float mult = (lc == 0 || lc == NLC - 1) ? 1.0f : 2.0f;
            float2* f = g_field + (size_t)grow * N_SW;
            const float* pj = g_pinj + (b * NM + m) * NV1;

            #pragma unroll
            for (int j = 0; j < 4; j++) {
                int t = lane + 32 * j;
                float fr = 0.f, fi = 0.f;
                if (step > 0) { float2 fv = f[t]; fr = fv.x; fi = fv.y; }
                if (inject && t < NV1) fr += pj[t] * w;
                float a1x, a1y, a2x, a2y;
                unpack2(acc1[r][j], a1x, a1y);
                unpack2(acc2[r][j], a2x, a2y);
                float gr = a1x - a2y;
                float gi = a1y + a2x;
                fr = fr * 0.85f + gr * 0.25f;
                fi = fi * 0.85f + gi * 0.25f;
                f[t] = make_float2(fr, fi);
                if (last && t >= 121) {
                    float sq  = fr * fr + fi * fi + 1e-8f;
                    float inv = rsqrtf(sq);
                    float mag = sq * inv;
                    float th  = fast_tanh(mag * gain_sh[t]);
                    float sc  = __fdividef(th, mag + 1e-8f);
                    float orr = fr * sc, oii = fi * sc;
                    g_erow[(t - 121) * ROWS + grow] = mult * (orr * orr + oii * oii);
                }
            }
            // tail t = 128..130 (no injection possible: t >= NV1)
            if (lane < 3) {
                int t = 128 + lane;
                float fr = 0.f, fi = 0.f;
                if (step > 0) { float2 fv = f[t]; fr = fv.x; fi = fv.y; }
                float gr = 0.f, gi = 0.f;
                if (step > 0) { float2 gv = gt[r * 3 + lane]; gr = gv.x; gi = gv.y; }
                fr = fr * 0.85f + gr * 0.25f;
                fi = fi * 0.85f + gi * 0.25f;
                f[t] = make_float2(fr, fi);
                if (last) {
                    float sq  = fr * fr + fi * fi + 1e-8f;
                    float inv = rsqrtf(sq);
                    float mag = sq * inv;
                    float th  = fast_tanh(mag * gain_sh[t]);
                    float sc  = __fdividef(th, mag + 1e-8f);
                    float orr = fr * sc, oii = fi * sc;
                    g_erow[(t - 121) * ROWS + grow] = mult * (orr * orr + oii * oii);
                }
            }
        }
        // warps own disjoint smem regions and rows: no block sync needed per tile
    }
}

// ---------------- readout ----------------
__global__ void k_final(const float* __restrict__ rw, const float* __restrict__ rb,
                        float* __restrict__ out) {
    __shared__ float feat[10];
    int b = blockIdx.x;
    int warp = threadIdx.x >> 5, lane = threadIdx.x & 31;
    if (warp < 10) {
        float s = 0.f;
        const float* e = g_erow + warp * ROWS + b * (NLC * NM);
        for (int k = lane; k < NLC * NM; k += 32) s += e[k];
        #pragma unroll
        for (int o = 16; o > 0; o >>= 1) s += __shfl_xor_sync(0xffffffffu, s, o);
        if (lane == 0) feat[warp] = log1pf(s + 1e-8f);
    }
    __syncthreads();
    if (threadIdx.x < 10) {
        int c = threadIdx.x;
        float acc = rb[c];
        #pragma unroll
        for (int o = 0; o < 10; o++) acc += feat[o] * rw[c * 10 + o];
        out[b * 10 + c] = acc;
    }
}

// ---------------- entry ----------------
extern "C" void kernel_launch(void* const* d_in, const int* in_sizes, int n_in,
                              void* d_out, int out_size) {
    const float* images = (const float*)d_in[0];
    const float* conn_r = (const float*)d_in[1];
    const float* conn_i = (const float*)d_in[2];
    const float* ph     = (const float*)d_in[3];
    const float* sg     = (const float*)d_in[4];
    const float* rw     = (const float*)d_in[5];
    const float* rb     = (const float*)d_in[6];
    const int*   nsp    = (const int*)d_in[7];
    const int*   injp   = (const int*)d_in[8];

    cudaFuncSetAttribute(k_step, cudaFuncAttributeMaxDynamicSharedMemorySize, SMEM_BYTES);

    k_init<<<1, 32>>>();
    const int n_img = BATCH * 28 * 28;
    k_absmax<<<(n_img + 511) / 512, 512>>>(images, n_img);
    k_prep<<<(NC2 + 255) / 256, 256>>>(conn_r, conn_i, ph, sg);
    k_pinj<<<(BATCH * NM * NV1 + 255) / 256, 256>>>(images);

    for (int t = 0; t < 10; t++)
        k_step<<<GRID, TPB, SMEM_BYTES>>>(t, nsp, injp);

    k_final<<<BATCH, 320>>>(rw, rb, (float*)d_out);
}

// round 5
// speedup vs baseline: 1.4311x; 1.0029x over previous
#include <cuda_runtime.h>
#include <math.h>

// ---------------- problem constants ----------------
#define N_SW   131
#define NC2    (N_SW*N_SW)        // 17161
#define NLC    33                 // distinct |L-32| classes 0..32
#define NM     16                 // only m<16 are nonzero
#define BATCH  128
#define NV1    49                 // injection switches [0,49)
#define ROWS   (BATCH*NLC*NM)     // 67584 independent 131-dim complex systems

// ---------------- step-kernel tiling ----------------
#define TPB    256
#define WARPS  8
#define RPW    6                  // rows per warp
#define RPB    (WARPS*RPW)        // 48 rows per tile
#define NTILE  (ROWS/RPB)         // 1408 (exact)
#define GRID   148                // persistent: one CTA per SM

// dynamic smem layout (bytes)
#define C_BYTES    (NC2*8)                    // 137288: C[s][t] as (Cr,Ci) u64
#define OUT_OFF    C_BYTES
#define OUT_BYTES  (WARPS*RPW*N_SW*8)         // 50304: per-warp out rows (packed u64)
#define GAIN_OFF   (OUT_OFF+OUT_BYTES)
#define GAIN_BYTES 544
#define TAIL_OFF   (GAIN_OFF+GAIN_BYTES)
#define TAIL_BYTES (WARPS*RPW*3*8)            // 1152: per-warp tail g (t=128..130) float2
#define SMEM_BYTES (TAIL_OFF+TAIL_BYTES)      // ~189 KB

// ---------------- persistent device scratch (no allocs allowed) ----------------
__device__ float2 g_field[(size_t)ROWS * N_SW];   // ~70.8 MB state
__device__ float2 g_C[NC2];                       // conn * e^{i*phase[t]}
__device__ float  g_gain[N_SW];                   // softplus(switch_gain)
__device__ float  g_pinj[BATCH * NM * NV1];       // 0.3/enc_max * p[b,s,m]
__device__ float  g_erow[10 * ROWS];              // per-row energy, final step
__device__ int    g_absmax_bits;

// ---------------- packed f32x2 helpers ----------------
typedef unsigned long long u64;
__device__ __forceinline__ u64 pack2(float x, float y) {
    u64 r; asm("mov.b64 %0, {%1,%2};" : "=l"(r) : "f"(x), "f"(y)); return r;
}
__device__ __forceinline__ void unpack2(u64 v, float& x, float& y) {
    asm("mov.b64 {%0,%1}, %2;" : "=f"(x), "=f"(y) : "l"(v));
}
#define FMA2(acc, a, b) asm("fma.rn.f32x2 %0, %1, %2, %0;" : "+l"(acc) : "l"(a), "l"(b))

// fast tanh via MUFU ex2 (clamped; ~1e-6 rel err)
__device__ __forceinline__ float fast_tanh(float x) {
    float xc = fminf(x, 15.f);
    float e = __expf(2.f * xc);
    return __fdividef(e - 1.f, e + 1.f);
}

// ---------------- prep kernels ----------------
__global__ void k_init() { if (threadIdx.x == 0) g_absmax_bits = 0; }

__global__ void k_absmax(const float* __restrict__ img, int n) {
    int i = blockIdx.x * blockDim.x + threadIdx.x;
    float v = (i < n) ? fabsf(img[i]) : 0.f;
    #pragma unroll
    for (int o = 16; o > 0; o >>= 1) v = fmaxf(v, __shfl_xor_sync(0xffffffffu, v, o));
    if ((threadIdx.x & 31) == 0) atomicMax(&g_absmax_bits, __float_as_int(v));
}

__global__ void k_prep(const float* __restrict__ cr, const float* __restrict__ ci,
                       const float* __restrict__ ph, const float* __restrict__ sg) {
    int i = blockIdx.x * blockDim.x + threadIdx.x;
    if (i < NC2) {
        int t = i % N_SW;
        float sp, cp;
        sincosf(ph[t], &sp, &cp);
        float a = cr[i], b = ci[i];
        g_C[i] = make_float2(a * cp - b * sp, a * sp + b * cp);
    }
    if (i < N_SW) {
        float x = sg[i];
        g_gain[i] = fmaxf(x, 0.f) + log1pf(expf(-fabsf(x)));   // stable softplus
    }
}

__global__ void k_pinj(const float* __restrict__ img) {
    int i = blockIdx.x * blockDim.x + threadIdx.x;
    if (i >= BATCH * NM * NV1) return;
    int b   = i / (NM * NV1);
    int rem = i - b * (NM * NV1);
    int m   = rem / NV1;
    int s   = rem - m * NV1;
    int pr = s / 7, pc = s - pr * 7;
    int ir = m >> 2, ic = m & 3;
    float am   = __int_as_float(g_absmax_bits);
    float coef = (am > 1e-8f) ? 0.3f / am : 0.3f;
    g_pinj[i] = coef * img[b * 784 + (pr * 4 + ir) * 28 + (pc * 4 + ic)];
}

// ---------------- main recurrence step (persistent) ----------------
__global__ __launch_bounds__(TPB, 1) void k_step(int step,
                                                 const int* __restrict__ nsp,
                                                 const int* __restrict__ injp) {
    extern __shared__ unsigned char smem[];
    u64*    Csh     = (u64*)(smem);
    u64*    out_sh  = (u64*)(smem + OUT_OFF);
    float*  gain_sh = (float*)(smem + GAIN_OFF);
    float2* tail_sh = (float2*)(smem + TAIL_OFF);

    const int ns = *nsp;
    if (step >= ns) return;
    const int injs = *injp;
    const bool inject = (step < injs);
    const bool last   = (step == ns - 1);

    // load C + gain once per CTA
    {
        const u64* Cg = (const u64*)g_C;
        for (int i = threadIdx.x; i < NC2; i += TPB) Csh[i] = Cg[i];
        for (int i = threadIdx.x; i < N_SW; i += TPB) gain_sh[i] = g_gain[i];
    }
    __syncthreads();

    const int warp = threadIdx.x >> 5;
    const int lane = threadIdx.x & 31;
    u64*    outw = out_sh  + (size_t)warp * RPW * N_SW;
    float2* gt   = tail_sh + (size_t)warp * RPW * 3;

    // tail mapping: lane -> (row r_t = lane/4, t-index tx = lane%4)
    // lanes with r_t >= RPW or tx == 3 are dud lanes: they must still execute
    // the FMAs (uniform control flow) but read a CLAMPED, in-bounds address
    // and never write back.
    const int  r_t    = lane >> 2;
    const int  tx     = lane & 3;
    const bool tvalid = (tx < 3) && (r_t < RPW);
    const int  r_tc   = (r_t < RPW) ? r_t : 0;       // SAFE row for reads
    const int  txc    = (tx  < 3)  ? tx  : 2;        // SAFE col for reads

    for (int tile = blockIdx.x; tile < NTILE; tile += GRID) {
        const int rowBase = tile * RPB + warp * RPW;

        u64 acc1[RPW][4], acc2[RPW][4];
        #pragma unroll
        for (int r = 0; r < RPW; r++)
            #pragma unroll
            for (int j = 0; j < 4; j++) { acc1[r][j] = 0ull; acc2[r][j] = 0ull; }
        u64 ta1 = 0ull, ta2 = 0ull;

        if (step > 0) {
            // ---- Phase A: out = field * tanh(|f|*g)/(|f|+eps), packed into smem ----
            #pragma unroll
            for (int r = 0; r < RPW; r++) {
                const float2* f = g_field + (size_t)(rowBase + r) * N_SW;
                #pragma unroll
                for (int j = 0; j < 5; j++) {
                    int t = lane + 32 * j;
                    if (t < N_SW) {
                        float2 fv = f[t];
                        float sq  = fv.x * fv.x + fv.y * fv.y + 1e-8f;
                        float inv = rsqrtf(sq);
                        float mag = sq * inv;                 // sqrt(sq)
                        float th  = fast_tanh(mag * gain_sh[t]);
                        float sc  = __fdividef(th, mag + 1e-8f);
                        outw[r * N_SW + t] = pack2(fv.x * sc, fv.y * sc);
                    }
                }
            }
            __syncwarp();

            // ---- Phase B: g[t] = sum_s out[s] * C[s][t], split accumulators ----
            // acc1 += (or,or)*(Cr,Ci);  acc2 += (oi,oi)*(Cr,Ci)
            // gr = acc1.lo - acc2.hi;   gi = acc1.hi + acc2.lo
            const u64* Ot = outw + (size_t)r_tc * N_SW;   // clamped tail row (in-bounds)
            for (int s = 0; s < N_SW; s++) {
                const u64* Crow = Csh + s * N_SW;
                u64 c0 = Crow[lane];
                u64 c1 = Crow[lane + 32];
                u64 c2 = Crow[lane + 64];
                u64 c3 = Crow[lane + 96];
                // tail columns t=128..130 (lane-partitioned, 1 row x 1 col per lane)
                {
                    float orr, oii;
                    unpack2(Ot[s], orr, oii);
                    u64 a1 = pack2(orr, orr);
                    u64 a2 = pack2(oii, oii);
                    u64 ct = Crow[128 + txc];
                    FMA2(ta1, a1, ct);
                    FMA2(ta2, a2, ct);
                }
                #pragma unroll
                for (int r = 0; r < RPW; r++) {
                    float orr, oii;
                    unpack2(outw[r * N_SW + s], orr, oii);
                    u64 a1 = pack2(orr, orr);
                    u64 a2 = pack2(oii, oii);
                    FMA2(acc1[r][0], a1, c0);
                    FMA2(acc2[r][0], a2, c0);
                    FMA2(acc1[r][1], a1, c1);
                    FMA2(acc2[r][1], a2, c1);
                    FMA2(acc1[r][2], a1, c2);
                    FMA2(acc2[r][2], a2, c2);
                    FMA2(acc1[r][3], a1, c3);
                    FMA2(acc2[r][3], a2, c3);
                }
            }
            // tail writeback (only valid lanes write)
            {
                float t1x, t1y, t2x, t2y;
                unpack2(ta1, t1x, t1y);
                unpack2(ta2, t2x, t2y);
                if (tvalid) gt[r_t * 3 + tx] = make_float2(t1x - t2y, t1y + t2x);
            }
            __syncwarp();
        }

        // ---- Phase C: field = field*0.85 + inj*w*0.85 + g*0.25; last -> energy ----
        #pragma unroll
        for (int r = 0; r < RPW; r++) {
            int grow = rowBase + r;
            int b    = grow / (NLC * NM);
            int rem  = grow - b * (NLC * NM);
            int lc   = rem >> 4;
            int m    = rem & 15;
            float w    = 1.0f - (float)lc * 0.015625f;             // 1 - d/64
            float mult = (lc == 0 || lc == NLC - 1) ? 1.0f : 2.0f;
            float2* f = g_field + (size_t)grow * N_SW;
            const float* pj = g_pinj + (b * NM + m) * NV1;

            #pragma unroll
            for (int j = 0; j < 4; j++) {
                int t = lane + 32 * j;
                float fr = 0.f, fi = 0.f;
                if (step > 0) { float2 fv = f[t]; fr = fv.x; fi = fv.y; }
                if (inject && t < NV1) fr += pj[t] * w;
                float a1x, a1y, a2x, a2y;
                unpack2(acc1[r][j], a1x, a1y);
                unpack2(acc2[r][j], a2x, a2y);
                float gr = a1x - a2y;
                float gi = a1y + a2x;
                fr = fr * 0.85f + gr * 0.25f;
                fi = fi * 0.85f + gi * 0.25f;
                f[t] = make_float2(fr, fi);
                if (last && t >= 121) {
                    float sq  = fr * fr + fi * fi + 1e-8f;
                    float inv = rsqrtf(sq);
                    float mag = sq * inv;
                    float th  = fast_tanh(mag * gain_sh[t]);
                    float sc  = __fdividef(th, mag + 1e-8f);
                    float orr = fr * sc, oii = fi * sc;
                    g_erow[(t - 121) * ROWS + grow] = mult * (orr * orr + oii * oii);
                }
            }
            // tail t = 128..130 (no injection possible: t >= NV1)
            if (lane < 3) {
                int t = 128 + lane;
                float fr = 0.f, fi = 0.f;
                if (step > 0) { float2 fv = f[t]; fr = fv.x; fi = fv.y; }
                float gr = 0.f, gi = 0.f;
                if (step > 0) { float2 gv = gt[r * 3 + lane]; gr = gv.x; gi = gv.y; }
                fr = fr * 0.85f + gr * 0.25f;
                fi = fi * 0.85f + gi * 0.25f;
                f[t] = make_float2(fr, fi);
                if (last) {
                    float sq  = fr * fr + fi * fi + 1e-8f;
                    float inv = rsqrtf(sq);
                    float mag = sq * inv;
                    float th  = fast_tanh(mag * gain_sh[t]);
                    float sc  = __fdividef(th, mag + 1e-8f);
                    float orr = fr * sc, oii = fi * sc;
                    g_erow[(t - 121) * ROWS + grow] = mult * (orr * orr + oii * oii);
                }
            }
        }
        // warps own disjoint smem regions and rows: no block sync needed per tile
    }
}

// ---------------- readout ----------------
__global__ void k_final(const float* __restrict__ rw, const float* __restrict__ rb,
                        float* __restrict__ out) {
    __shared__ float feat[10];
    int b = blockIdx.x;
    int warp = threadIdx.x >> 5, lane = threadIdx.x & 31;
    if (warp < 10) {
        float s = 0.f;
        const float* e = g_erow + warp * ROWS + b * (NLC * NM);
        for (int k = lane; k < NLC * NM; k += 32) s += e[k];
        #pragma unroll
        for (int o = 16; o > 0; o >>= 1) s += __shfl_xor_sync(0xffffffffu, s, o);
        if (lane == 0) feat[warp] = log1pf(s + 1e-8f);
    }
    __syncthreads();
    if (threadIdx.x < 10) {
        int c = threadIdx.x;
        float acc = rb[c];
        #pragma unroll
        for (int o = 0; o < 10; o++) acc += feat[o] * rw[c * 10 + o];
        out[b * 10 + c] = acc;
    }
}

// ---------------- entry ----------------
extern "C" void kernel_launch(void* const* d_in, const int* in_sizes, int n_in,
                              void* d_out, int out_size) {
    const float* images = (const float*)d_in[0];
    const float* conn_r = (const float*)d_in[1];
    const float* conn_i = (const float*)d_in[2];
    const float* ph     = (const float*)d_in[3];
    const float* sg     = (const float*)d_in[4];
    const float* rw     = (const float*)d_in[5];
    const float* rb     = (const float*)d_in[6];
    const int*   nsp    = (const int*)d_in[7];
    const int*   injp   = (const int*)d_in[8];

    cudaFuncSetAttribute(k_step, cudaFuncAttributeMaxDynamicSharedMemorySize, SMEM_BYTES);

    k_init<<<1, 32>>>();
    const int n_img = BATCH * 28 * 28;
    k_absmax<<<(n_img + 511) / 512, 512>>>(images, n_img);
    k_prep<<<(NC2 + 255) / 256, 256>>>(conn_r, conn_i, ph, sg);
    k_pinj<<<(BATCH * NM * NV1 + 255) / 256, 256>>>(images);

    for (int t = 0; t < 10; t++)
        k_step<<<GRID, TPB, SMEM_BYTES>>>(t, nsp, injp);

    k_final<<<BATCH, 320>>>(rw, rb, (float*)d_out);
}

// round 7
// speedup vs baseline: 1.5778x; 1.1025x over previous
#include <cuda_runtime.h>
#include <cuda_bf16.h>
#include <math.h>

// ---------------- problem constants ----------------
#define N_SW   131
#define NLC    33                 // distinct |L-32| classes
#define NM     16                 // only m<16 nonzero
#define BATCH  128
#define NV1    49
#define ROWS   (BATCH*NLC*NM)     // 67584

// ---------------- GEMM formulation ----------------
// A[row][k], k in [0,288): k<144 -> O_r (s=k, valid s<131), k>=144 -> O_i (s=k-144)
// S[k][t] (288 x 136): k<131 -> C_r[k][t]; 144<=k<275 -> -C_i[k-144][t]; else 0
// G_r = A*S ; G_i = A*B_i with B_i(k-tile kt) = (kt<9 ? -S[kt+9] : S[kt-9])
#define KHALF  144
#define KDIM   288
#define NDIM   136
#define SSTRIDE_B 272             // bytes per S row (136 bf16), 17*16 -> ldsm-aligned
#define ASTRIDE_B 592             // bytes per A row, 37*16 -> ldsm-aligned, conflict-free
#define CHUNK  64
#define NCHUNK (ROWS/CHUNK)       // 1056 exact
#define GRID   148
#define TPB    256

#define S_BYTES  (KDIM*NDIM*2)    // 78336
#define S_HI_OFF 0
#define S_LO_OFF S_BYTES
#define A_HI_OFF (2*S_BYTES)      // 156672
#define A_BYTES  (CHUNK*ASTRIDE_B)// 37888
#define A_LO_OFF (A_HI_OFF + A_BYTES)
#define SMEM_BYTES (A_LO_OFF + A_BYTES)   // 232448 == 227KB opt-in max
#define G_OFF    A_HI_OFF         // g overlay: 64 x 288 fp32 = 73728 <= 75776
#define GSTRIDE  288              // floats per g row

// ---------------- persistent device scratch ----------------
__device__ float2 g_field[(size_t)ROWS * N_SW];
__device__ __align__(16) __nv_bfloat16 g_S_hi[KDIM * NDIM];
__device__ __align__(16) __nv_bfloat16 g_S_lo[KDIM * NDIM];
__device__ float  g_gain[N_SW];
__device__ float  g_pinj[BATCH * NM * NV1];
__device__ float  g_erow[10 * ROWS];
__device__ int    g_absmax_bits;

// ---------------- helpers ----------------
__device__ __forceinline__ unsigned smem_addr(const void* p) {
    unsigned a;
    asm("{ .reg .u64 t; cvta.to.shared.u64 t, %1; cvt.u32.u64 %0, t; }" : "=r"(a) : "l"(p));
    return a;
}
#define LDSM4(R, addr) \
    asm volatile("ldmatrix.sync.aligned.m8n8.x4.shared.b16 {%0,%1,%2,%3}, [%4];" \
        : "=r"((R)[0]), "=r"((R)[1]), "=r"((R)[2]), "=r"((R)[3]) : "r"(addr))
#define LDSM2T(R, addr) \
    asm volatile("ldmatrix.sync.aligned.m8n8.x2.trans.shared.b16 {%0,%1}, [%2];" \
        : "=r"((R)[0]), "=r"((R)[1]) : "r"(addr))
#define MMA_BF16(C, A, B) \
    asm volatile("mma.sync.aligned.m16n8k16.row.col.f32.bf16.bf16.f32 " \
        "{%0,%1,%2,%3}, {%4,%5,%6,%7}, {%8,%9}, {%0,%1,%2,%3};" \
        : "+f"((C)[0]), "+f"((C)[1]), "+f"((C)[2]), "+f"((C)[3]) \
        : "r"((A)[0]), "r"((A)[1]), "r"((A)[2]), "r"((A)[3]), "r"((B)[0]), "r"((B)[1]))

__device__ __forceinline__ float fast_tanh(float x) {
    float xc = fminf(x, 15.f);
    float e = __expf(2.f * xc);
    return __fdividef(e - 1.f, e + 1.f);
}
__device__ __forceinline__ void store_split(unsigned short* ah, unsigned short* al,
                                            int idx, float v) {
    __nv_bfloat16 h = __float2bfloat16(v);
    float hf = __bfloat162float(h);
    __nv_bfloat16 l = __float2bfloat16(v - hf);
    ah[idx] = __bfloat16_as_ushort(h);
    al[idx] = __bfloat16_as_ushort(l);
}

// ---------------- prep kernels ----------------
__global__ void k_init() { if (threadIdx.x == 0) g_absmax_bits = 0; }

__global__ void k_absmax(const float* __restrict__ img, int n) {
    int i = blockIdx.x * blockDim.x + threadIdx.x;
    float v = (i < n) ? fabsf(img[i]) : 0.f;
    #pragma unroll
    for (int o = 16; o > 0; o >>= 1) v = fmaxf(v, __shfl_xor_sync(0xffffffffu, v, o));
    if ((threadIdx.x & 31) == 0) atomicMax(&g_absmax_bits, __float_as_int(v));
}

__global__ void k_prepS(const float* __restrict__ cr, const float* __restrict__ ci,
                        const float* __restrict__ ph, const float* __restrict__ sg) {
    int i = blockIdx.x * blockDim.x + threadIdx.x;
    if (i < KDIM * NDIM) {
        int k = i / NDIM, t = i % NDIM;
        float val = 0.f;
        if (t < N_SW) {
            float sp, cp;
            sincosf(ph[t], &sp, &cp);
            if (k < N_SW) {
                float a = cr[k * N_SW + t], b = ci[k * N_SW + t];
                val = a * cp - b * sp;                       // C_r
            } else if (k >= KHALF && k < KHALF + N_SW) {
                int s = k - KHALF;
                float a = cr[s * N_SW + t], b = ci[s * N_SW + t];
                val = -(a * sp + b * cp);                    // -C_i
            }
        }
        __nv_bfloat16 h = __float2bfloat16(val);
        float hf = __bfloat162float(h);
        g_S_hi[i] = h;
        g_S_lo[i] = __float2bfloat16(val - hf);
    }
    if (i < N_SW) {
        float x = sg[i];
        g_gain[i] = fmaxf(x, 0.f) + log1pf(expf(-fabsf(x)));
    }
}

__global__ void k_pinj(const float* __restrict__ img) {
    int i = blockIdx.x * blockDim.x + threadIdx.x;
    if (i >= BATCH * NM * NV1) return;
    int b   = i / (NM * NV1);
    int rem = i - b * (NM * NV1);
    int m   = rem / NV1;
    int s   = rem - m * NV1;
    int pr = s / 7, pc = s - pr * 7;
    int ir = m >> 2, ic = m & 3;
    float am   = __int_as_float(g_absmax_bits);
    float coef = (am > 1e-8f) ? 0.3f / am : 0.3f;
    g_pinj[i] = coef * img[b * 784 + (pr * 4 + ir) * 28 + (pc * 4 + ic)];
}

// ---------------- main recurrence step ----------------
__global__ __launch_bounds__(TPB, 1) void k_step(int step,
                                                 const int* __restrict__ nsp,
                                                 const int* __restrict__ injp) {
    extern __shared__ unsigned char smem[];
    const int ns = *nsp;
    if (step >= ns) return;
    const int injs = *injp;
    const bool inject = (step < injs);
    const bool last   = (step == ns - 1);

    // load S hi/lo into smem (once per CTA per step)
    {
        const uint4* sh = (const uint4*)g_S_hi;
        const uint4* sl = (const uint4*)g_S_lo;
        uint4* dh = (uint4*)(smem + S_HI_OFF);
        uint4* dl = (uint4*)(smem + S_LO_OFF);
        for (int i = threadIdx.x; i < S_BYTES / 16; i += TPB) { dh[i] = sh[i]; dl[i] = sl[i]; }
    }
    const int warp = threadIdx.x >> 5;
    const int lane = threadIdx.x & 31;
    const int mtp    = warp >> 2;    // 0/1: covers m-tiles {2mtp, 2mtp+1}
    const int nlane4 = warp & 3;     // ntG = nlane4 + 4q

    float gain_reg[5];
    #pragma unroll
    for (int j = 0; j < 5; j++) {
        int t = lane + 32 * j;
        gain_reg[j] = (t < N_SW) ? g_gain[t] : 0.f;
    }
    __syncthreads();

    const unsigned smem_base = smem_addr(smem);

    for (int chunk = blockIdx.x; chunk < NCHUNK; chunk += GRID) {
        const int rowBase = chunk * CHUNK;

        if (step > 0) {
            // ---- Phase A: out = field*tanh(|f|g)/(|f|+eps) -> A hi/lo bf16 smem ----
            for (int r = 0; r < 8; r++) {
                int lrow = warp * 8 + r;
                const float2* f = g_field + (size_t)(rowBase + lrow) * N_SW;
                unsigned short* ah = (unsigned short*)(smem + A_HI_OFF + lrow * ASTRIDE_B);
                unsigned short* al = (unsigned short*)(smem + A_LO_OFF + lrow * ASTRIDE_B);
                #pragma unroll
                for (int j = 0; j < 5; j++) {
                    int t = lane + 32 * j;
                    if (t < KHALF) {
                        float orr = 0.f, oii = 0.f;
                        if (t < N_SW) {
                            float2 fv = f[t];
                            float sq  = fv.x * fv.x + fv.y * fv.y + 1e-8f;
                            float inv = rsqrtf(sq);
                            float mag = sq * inv;
                            float th  = fast_tanh(mag * gain_reg[j]);
                            float sc  = __fdividef(th, mag + 1e-8f);
                            orr = fv.x * sc; oii = fv.y * sc;
                        }
                        store_split(ah, al, t, orr);
                        store_split(ah, al, KHALF + t, oii);
                    }
                }
            }
            __syncthreads();

            // ---- Phase B: bf16-split mma, 3 passes (HH + HL + LH) ----
            float acc[18][4];
            #pragma unroll
            for (int i = 0; i < 18; i++)
                #pragma unroll
                for (int c = 0; c < 4; c++) acc[i][c] = 0.f;

            for (int kt = 0; kt < 18; kt++) {
                unsigned aH[2][4], aL[2][4];
                #pragma unroll
                for (int mi = 0; mi < 2; mi++) {
                    int mta = 2 * mtp + mi;
                    unsigned arow = (lane & 15) + 16 * mta;
                    unsigned acol = 16 * kt + ((lane >> 4) << 3);
                    unsigned addrH = smem_base + A_HI_OFF + arow * ASTRIDE_B + acol * 2;
                    LDSM4(aH[mi], addrH);
                    LDSM4(aL[mi], addrH + (unsigned)A_BYTES);
                }
                #pragma unroll
                for (int q = 0; q < 9; q++) {
                    int ntG = nlane4 + 4 * q;
                    if (ntG > 33) ntG = 33;                  // dup tiles: benign
                    int G  = (ntG >= 17) ? 1 : 0;
                    int nt = ntG - 17 * G;
                    int kts = G ? ((kt < 9) ? kt + 9 : kt - 9) : kt;
                    bool neg = (G && kt < 9);
                    unsigned baddr = smem_base + S_HI_OFF
                                   + (16 * kts + (lane & 15)) * SSTRIDE_B + nt * 16;
                    unsigned bh[2], bl[2];
                    LDSM2T(bh, baddr);
                    LDSM2T(bl, baddr + (unsigned)S_BYTES);
                    if (neg) {
                        bh[0] ^= 0x80008000u; bh[1] ^= 0x80008000u;
                        bl[0] ^= 0x80008000u; bl[1] ^= 0x80008000u;
                    }
                    #pragma unroll
                    for (int mi = 0; mi < 2; mi++) {
                        MMA_BF16(acc[q * 2 + mi], aH[mi], bh);
                        MMA_BF16(acc[q * 2 + mi], aH[mi], bl);
                        MMA_BF16(acc[q * 2 + mi], aL[mi], bh);
                    }
                }
            }
            __syncthreads();

            // ---- store g fragments (overlay A region) ----
            float* gsm = (float*)(smem + G_OFF);
            #pragma unroll
            for (int q = 0; q < 9; q++) {
                int ntG = nlane4 + 4 * q;
                if (ntG > 33) ntG = 33;
                int G  = (ntG >= 17) ? 1 : 0;
                int nt = ntG - 17 * G;
                int colBase = G * KHALF + nt * 8 + (lane & 3) * 2;
                #pragma unroll
                for (int mi = 0; mi < 2; mi++) {
                    int row0 = 16 * (2 * mtp + mi) + (lane >> 2);
                    float* a = acc[q * 2 + mi];
                    *(float2*)&gsm[row0 * GSTRIDE + colBase]       = make_float2(a[0], a[1]);
                    *(float2*)&gsm[(row0 + 8) * GSTRIDE + colBase] = make_float2(a[2], a[3]);
                }
            }
            __syncthreads();
        }

        // ---- Phase C: field = field*0.85 + inj*w + g*0.25 ; last -> energy ----
        {
            const float* gsm = (const float*)(smem + G_OFF);
            for (int r = 0; r < 8; r++) {
                int lrow = warp * 8 + r;
                int grow = rowBase + lrow;
                int b    = grow / (NLC * NM);
                int rem  = grow - b * (NLC * NM);
                int lc   = rem >> 4;
                int m    = rem & 15;
                float w    = 1.0f - (float)lc * 0.015625f;
                float mult = (lc == 0 || lc == NLC - 1) ? 1.0f : 2.0f;
                float2* f = g_field + (size_t)grow * N_SW;
                const float* pj = g_pinj + (b * NM + m) * NV1;
                #pragma unroll
                for (int j = 0; j < 5; j++) {
                    int t = lane + 32 * j;
                    if (t < N_SW) {
                        float fr = 0.f, fi = 0.f;
                        if (step > 0) { float2 fv = f[t]; fr = fv.x; fi = fv.y; }
                        if (inject && t < NV1) fr += pj[t] * w;
                        float gr = 0.f, gi = 0.f;
                        if (step > 0) {
                            gr = gsm[lrow * GSTRIDE + t];
                            gi = gsm[lrow * GSTRIDE + KHALF + t];
                        }
                        fr = fr * 0.85f + gr * 0.25f;
                        fi = fi * 0.85f + gi * 0.25f;
                        f[t] = make_float2(fr, fi);
                        if (last && t >= 121) {
                            float sq  = fr * fr + fi * fi + 1e-8f;
                            float inv = rsqrtf(sq);
                            float mag = sq * inv;
                            float th  = fast_tanh(mag * gain_reg[j]);
                            float sc  = __fdividef(th, mag + 1e-8f);
                            float orr = fr * sc, oii = fi * sc;
                            g_erow[(t - 121) * ROWS + grow] = mult * (orr * orr + oii * oii);
                        }
                    }
                }
            }
        }
        if (step > 0) __syncthreads();   // protect A/g overlay before next chunk
    }
}

// ---------------- readout ----------------
__global__ void k_final(const float* __restrict__ rw, const float* __restrict__ rb,
                        float* __restrict__ out) {
    __shared__ float feat[10];
    int b = blockIdx.x;
    int warp = threadIdx.x >> 5, lane = threadIdx.x & 31;
    if (warp < 10) {
        float s = 0.f;
        const float* e = g_erow + warp * ROWS + b * (NLC * NM);
        for (int k = lane; k < NLC * NM; k += 32) s += e[k];
        #pragma unroll
        for (int o = 16; o > 0; o >>= 1) s += __shfl_xor_sync(0xffffffffu, s, o);
        if (lane == 0) feat[warp] = log1pf(s + 1e-8f);
    }
    __syncthreads();
    if (threadIdx.x < 10) {
        int c = threadIdx.x;
        float acc = rb[c];
        #pragma unroll
        for (int o = 0; o < 10; o++) acc += feat[o] * rw[c * 10 + o];
        out[b * 10 + c] = acc;
    }
}

// ---------------- entry ----------------
extern "C" void kernel_launch(void* const* d_in, const int* in_sizes, int n_in,
                              void* d_out, int out_size) {
    const float* images = (const float*)d_in[0];
    const float* conn_r = (const float*)d_in[1];
    const float* conn_i = (const float*)d_in[2];
    const float* ph     = (const float*)d_in[3];
    const float* sg     = (const float*)d_in[4];
    const float* rw     = (const float*)d_in[5];
    const float* rb     = (const float*)d_in[6];
    const int*   nsp    = (const int*)d_in[7];
    const int*   injp   = (const int*)d_in[8];

    cudaFuncSetAttribute(k_step, cudaFuncAttributeMaxDynamicSharedMemorySize, SMEM_BYTES);

    k_init<<<1, 32>>>();
    const int n_img = BATCH * 28 * 28;
    k_absmax<<<(n_img + 511) / 512, 512>>>(images, n_img);
    k_prepS<<<(KDIM * NDIM + 255) / 256, 256>>>(conn_r, conn_i, ph, sg);
    k_pinj<<<(BATCH * NM * NV1 + 255) / 256, 256>>>(images);

    for (int t = 0; t < 10; t++)
        k_step<<<GRID, TPB, SMEM_BYTES>>>(t, nsp, injp);

    k_final<<<BATCH, 320>>>(rw, rb, (float*)d_out);
}

// round 8
// speedup vs baseline: 1.5964x; 1.0118x over previous
#include <cuda_runtime.h>
#include <cuda_bf16.h>
#include <math.h>

// ---------------- problem constants ----------------
#define N_SW   131
#define NLC    33                 // distinct |L-32| classes
#define NM     16                 // only m<16 nonzero
#define BATCH  128
#define NV1    49
#define ROWS   (BATCH*NLC*NM)     // 67584

// ---------------- GEMM formulation ----------------
// A[row][k], k in [0,288): k<144 -> O_r (s=k, valid s<131), k>=144 -> O_i (s=k-144)
// S[k][t] (288 x 136): k<131 -> C_r[k][t]; 144<=k<275 -> -C_i[k-144][t]; else 0
// G_r = A*S ; G_i = A*B_i with B_i(k-tile kt) = (kt<9 ? -S[kt+9] : S[kt-9])
#define KHALF  144
#define KDIM   288
#define NDIM   136
#define SSTRIDE_B 272             // bytes per S row (136 bf16), 17*16 -> ldsm-aligned
#define ASTRIDE_B 592             // bytes per A row, 37*16 -> ldsm-aligned, conflict-free
#define CHUNK  64
#define NCHUNK (ROWS/CHUNK)       // 1056 exact
#define GRID   148
#define TPB    256

#define S_BYTES  (KDIM*NDIM*2)    // 78336
#define S_HI_OFF 0
#define S_LO_OFF S_BYTES
#define A_HI_OFF (2*S_BYTES)      // 156672
#define A_BYTES  (CHUNK*ASTRIDE_B)// 37888
#define A_LO_OFF (A_HI_OFF + A_BYTES)
#define SMEM_BYTES (A_LO_OFF + A_BYTES)   // 232448 == 227KB opt-in max
#define G_OFF    A_HI_OFF         // g overlay: 64 x 288 fp32 = 73728 <= 75776
#define GSTRIDE  288              // floats per g row

// ---------------- persistent device scratch ----------------
__device__ float2 g_field[(size_t)ROWS * N_SW];
__device__ __align__(16) __nv_bfloat16 g_S_hi[KDIM * NDIM];
__device__ __align__(16) __nv_bfloat16 g_S_lo[KDIM * NDIM];
__device__ float  g_gain[N_SW];
__device__ float  g_pinj[BATCH * NM * NV1];
__device__ float  g_erow[10 * ROWS];
__device__ int    g_absmax_bits;

// ---------------- helpers ----------------
__device__ __forceinline__ unsigned smem_addr(const void* p) {
    unsigned a;
    asm("{ .reg .u64 t; cvta.to.shared.u64 t, %1; cvt.u32.u64 %0, t; }" : "=r"(a) : "l"(p));
    return a;
}
#define LDSM4(R, addr) \
    asm volatile("ldmatrix.sync.aligned.m8n8.x4.shared.b16 {%0,%1,%2,%3}, [%4];" \
        : "=r"((R)[0]), "=r"((R)[1]), "=r"((R)[2]), "=r"((R)[3]) : "r"(addr))
#define LDSM2T(R, addr) \
    asm volatile("ldmatrix.sync.aligned.m8n8.x2.trans.shared.b16 {%0,%1}, [%2];" \
        : "=r"((R)[0]), "=r"((R)[1]) : "r"(addr))
#define MMA_BF16(C, A, B) \
    asm volatile("mma.sync.aligned.m16n8k16.row.col.f32.bf16.bf16.f32 " \
        "{%0,%1,%2,%3}, {%4,%5,%6,%7}, {%8,%9}, {%0,%1,%2,%3};" \
        : "+f"((C)[0]), "+f"((C)[1]), "+f"((C)[2]), "+f"((C)[3]) \
        : "r"((A)[0]), "r"((A)[1]), "r"((A)[2]), "r"((A)[3]), "r"((B)[0]), "r"((B)[1]))

__device__ __forceinline__ float fast_tanh(float x) {
    float xc = fminf(x, 15.f);
    float e = __expf(2.f * xc);
    return __fdividef(e - 1.f, e + 1.f);
}
__device__ __forceinline__ void store_split(unsigned short* ah, unsigned short* al,
                                            int idx, float v) {
    __nv_bfloat16 h = __float2bfloat16(v);
    float hf = __bfloat162float(h);
    __nv_bfloat16 l = __float2bfloat16(v - hf);
    ah[idx] = __bfloat16_as_ushort(h);
    al[idx] = __bfloat16_as_ushort(l);
}

// ---------------- prep kernels ----------------
__global__ void k_init() { if (threadIdx.x == 0) g_absmax_bits = 0; }

__global__ void k_absmax(const float* __restrict__ img, int n) {
    int i = blockIdx.x * blockDim.x + threadIdx.x;
    float v = (i < n) ? fabsf(img[i]) : 0.f;
    #pragma unroll
    for (int o = 16; o > 0; o >>= 1) v = fmaxf(v, __shfl_xor_sync(0xffffffffu, v, o));
    if ((threadIdx.x & 31) == 0) atomicMax(&g_absmax_bits, __float_as_int(v));
}

__global__ void k_prepS(const float* __restrict__ cr, const float* __restrict__ ci,
                        const float* __restrict__ ph, const float* __restrict__ sg) {
    int i = blockIdx.x * blockDim.x + threadIdx.x;
    if (i < KDIM * NDIM) {
        int k = i / NDIM, t = i % NDIM;
        float val = 0.f;
        if (t < N_SW) {
            float sp, cp;
            sincosf(ph[t], &sp, &cp);
            if (k < N_SW) {
                float a = cr[k * N_SW + t], b = ci[k * N_SW + t];
                val = a * cp - b * sp;                       // C_r
            } else if (k >= KHALF && k < KHALF + N_SW) {
                int s = k - KHALF;
                float a = cr[s * N_SW + t], b = ci[s * N_SW + t];
                val = -(a * sp + b * cp);                    // -C_i
            }
        }
        __nv_bfloat16 h = __float2bfloat16(val);
        float hf = __bfloat162float(h);
        g_S_hi[i] = h;
        g_S_lo[i] = __float2bfloat16(val - hf);
    }
    if (i < N_SW) {
        float x = sg[i];
        g_gain[i] = fmaxf(x, 0.f) + log1pf(expf(-fabsf(x)));
    }
}

__global__ void k_pinj(const float* __restrict__ img) {
    int i = blockIdx.x * blockDim.x + threadIdx.x;
    if (i >= BATCH * NM * NV1) return;
    int b   = i / (NM * NV1);
    int rem = i - b * (NM * NV1);
    int m   = rem / NV1;
    int s   = rem - m * NV1;
    int pr = s / 7, pc = s - pr * 7;
    int ir = m >> 2, ic = m & 3;
    float am   = __int_as_float(g_absmax_bits);
    float coef = (am > 1e-8f) ? 0.3f / am : 0.3f;
    g_pinj[i] = coef * img[b * 784 + (pr * 4 + ir) * 28 + (pc * 4 + ic)];
}

// ---------------- main recurrence step ----------------
__global__ __launch_bounds__(TPB, 1) void k_step(int step,
                                                 const int* __restrict__ nsp,
                                                 const int* __restrict__ injp) {
    extern __shared__ unsigned char smem[];
    const int ns = *nsp;
    if (step >= ns) return;
    const int injs = *injp;
    const bool inject = (step < injs);
    const bool last   = (step == ns - 1);

    // load S hi/lo into smem (once per CTA per step)
    {
        const uint4* sh = (const uint4*)g_S_hi;
        const uint4* sl = (const uint4*)g_S_lo;
        uint4* dh = (uint4*)(smem + S_HI_OFF);
        uint4* dl = (uint4*)(smem + S_LO_OFF);
        for (int i = threadIdx.x; i < S_BYTES / 16; i += TPB) { dh[i] = sh[i]; dl[i] = sl[i]; }
    }
    const int warp = threadIdx.x >> 5;
    const int lane = threadIdx.x & 31;
    const int mtp    = warp >> 2;    // 0/1: covers m-tiles {2mtp, 2mtp+1}
    const int nlane4 = warp & 3;     // ntG = nlane4 + 4q

    float gain_reg[5];
    #pragma unroll
    for (int j = 0; j < 5; j++) {
        int t = lane + 32 * j;
        gain_reg[j] = (t < N_SW) ? g_gain[t] : 0.f;
    }
    __syncthreads();

    const unsigned smem_base = smem_addr(smem);

    for (int chunk = blockIdx.x; chunk < NCHUNK; chunk += GRID) {
        const int rowBase = chunk * CHUNK;

        if (step > 0) {
            // ---- Phase A: out = field*tanh(|f|g)/(|f|+eps) -> A hi/lo bf16 smem ----
            for (int r = 0; r < 8; r++) {
                int lrow = warp * 8 + r;
                const float2* f = g_field + (size_t)(rowBase + lrow) * N_SW;
                unsigned short* ah = (unsigned short*)(smem + A_HI_OFF + lrow * ASTRIDE_B);
                unsigned short* al = (unsigned short*)(smem + A_LO_OFF + lrow * ASTRIDE_B);
                #pragma unroll
                for (int j = 0; j < 5; j++) {
                    int t = lane + 32 * j;
                    if (t < KHALF) {
                        float orr = 0.f, oii = 0.f;
                        if (t < N_SW) {
                            float2 fv = f[t];
                            float sq  = fv.x * fv.x + fv.y * fv.y + 1e-8f;
                            float inv = rsqrtf(sq);
                            float mag = sq * inv;
                            float th  = fast_tanh(mag * gain_reg[j]);
                            float sc  = __fdividef(th, mag + 1e-8f);
                            orr = fv.x * sc; oii = fv.y * sc;
                        }
                        store_split(ah, al, t, orr);
                        store_split(ah, al, KHALF + t, oii);
                    }
                }
            }
            __syncthreads();

            // ---- Phase B: bf16-split mma, 3 passes (HH + HL + LH) ----
            float acc[18][4];
            #pragma unroll
            for (int i = 0; i < 18; i++)
                #pragma unroll
                for (int c = 0; c < 4; c++) acc[i][c] = 0.f;

            for (int kt = 0; kt < 18; kt++) {
                unsigned aH[2][4], aL[2][4];
                #pragma unroll
                for (int mi = 0; mi < 2; mi++) {
                    int mta = 2 * mtp + mi;
                    unsigned arow = (lane & 15) + 16 * mta;
                    unsigned acol = 16 * kt + ((lane >> 4) << 3);
                    unsigned addrH = smem_base + A_HI_OFF + arow * ASTRIDE_B + acol * 2;
                    LDSM4(aH[mi], addrH);
                    LDSM4(aL[mi], addrH + (unsigned)A_BYTES);
                }
                #pragma unroll
                for (int q = 0; q < 9; q++) {
                    int ntG = nlane4 + 4 * q;
                    if (ntG > 33) ntG = 33;                  // dup tiles: benign
                    int G  = (ntG >= 17) ? 1 : 0;
                    int nt = ntG - 17 * G;
                    int kts = G ? ((kt < 9) ? kt + 9 : kt - 9) : kt;
                    bool neg = (G && kt < 9);
                    unsigned baddr = smem_base + S_HI_OFF
                                   + (16 * kts + (lane & 15)) * SSTRIDE_B + nt * 16;
                    unsigned bh[2], bl[2];
                    LDSM2T(bh, baddr);
                    LDSM2T(bl, baddr + (unsigned)S_BYTES);
                    if (neg) {
                        bh[0] ^= 0x80008000u; bh[1] ^= 0x80008000u;
                        bl[0] ^= 0x80008000u; bl[1] ^= 0x80008000u;
                    }
                    #pragma unroll
                    for (int mi = 0; mi < 2; mi++) {
                        MMA_BF16(acc[q * 2 + mi], aH[mi], bh);
                        MMA_BF16(acc[q * 2 + mi], aH[mi], bl);
                        MMA_BF16(acc[q * 2 + mi], aL[mi], bh);
                    }
                }
            }
            __syncthreads();

            // ---- store g fragments (overlay A region) ----
            float* gsm = (float*)(smem + G_OFF);
            #pragma unroll
            for (int q = 0; q < 9; q++) {
                int ntG = nlane4 + 4 * q;
                if (ntG > 33) ntG = 33;
                int G  = (ntG >= 17) ? 1 : 0;
                int nt = ntG - 17 * G;
                int colBase = G * KHALF + nt * 8 + (lane & 3) * 2;
                #pragma unroll
                for (int mi = 0; mi < 2; mi++) {
                    int row0 = 16 * (2 * mtp + mi) + (lane >> 2);
                    float* a = acc[q * 2 + mi];
                    *(float2*)&gsm[row0 * GSTRIDE + colBase]       = make_float2(a[0], a[1]);
                    *(float2*)&gsm[(row0 + 8) * GSTRIDE + colBase] = make_float2(a[2], a[3]);
                }
            }
            __syncthreads();
        }

        // ---- Phase C: field = field*0.85 + inj*w + g*0.25 ; last -> energy ----
        {
            const float* gsm = (const float*)(smem + G_OFF);
            for (int r = 0; r < 8; r++) {
                int lrow = warp * 8 + r;
                int grow = rowBase + lrow;
                int b    = grow / (NLC * NM);
                int rem  = grow - b * (NLC * NM);
                int lc   = rem >> 4;
                int m    = rem & 15;
                float w    = 1.0f - (float)lc * 0.015625f;
                float mult = (lc == 0 || lc == NLC - 1) ? 1.0f : 2.0f;
                float2* f = g_field + (size_t)grow * N_SW;
                const float* pj = g_pinj + (b * NM + m) * NV1;
                #pragma unroll
                for (int j = 0; j < 5; j++) {
                    int t = lane + 32 * j;
                    if (t < N_SW) {
                        float fr = 0.f, fi = 0.f;
                        if (step > 0) { float2 fv = f[t]; fr = fv.x; fi = fv.y; }
                        if (inject && t < NV1) fr += pj[t] * w;
                        float gr = 0.f, gi = 0.f;
                        if (step > 0) {
                            gr = gsm[lrow * GSTRIDE + t];
                            gi = gsm[lrow * GSTRIDE + KHALF + t];
                        }
                        fr = fr * 0.85f + gr * 0.25f;
                        fi = fi * 0.85f + gi * 0.25f;
                        f[t] = make_float2(fr, fi);
                        if (last && t >= 121) {
                            float sq  = fr * fr + fi * fi + 1e-8f;
                            float inv = rsqrtf(sq);
                            float mag = sq * inv;
                            float th  = fast_tanh(mag * gain_reg[j]);
                            float sc  = __fdividef(th, mag + 1e-8f);
                            float orr = fr * sc, oii = fi * sc;
                            g_erow[(t - 121) * ROWS + grow] = mult * (orr * orr + oii * oii);
                        }
                    }
                }
            }
        }
        if (step > 0) __syncthreads();   // protect A/g overlay before next chunk
    }
}

// ---------------- readout ----------------
__global__ void k_final(const float* __restrict__ rw, const float* __restrict__ rb,
                        float* __restrict__ out) {
    __shared__ float feat[10];
    int b = blockIdx.x;
    int warp = threadIdx.x >> 5, lane = threadIdx.x & 31;
    if (warp < 10) {
        float s = 0.f;
        const float* e = g_erow + warp * ROWS + b * (NLC * NM);
        for (int k = lane; k < NLC * NM; k += 32) s += e[k];
        #pragma unroll
        for (int o = 16; o > 0; o >>= 1) s += __shfl_xor_sync(0xffffffffu, s, o);
        if (lane == 0) feat[warp] = log1pf(s + 1e-8f);
    }
    __syncthreads();
    if (threadIdx.x < 10) {
        int c = threadIdx.x;
        float acc = rb[c];
        #pragma unroll
        for (int o = 0; o < 10; o++) acc += feat[o] * rw[c * 10 + o];
        out[b * 10 + c] = acc;
    }
}

// ---------------- entry ----------------
extern "C" void kernel_launch(void* const* d_in, const int* in_sizes, int n_in,
                              void* d_out, int out_size) {
    const float* images = (const float*)d_in[0];
    const float* conn_r = (const float*)d_in[1];
    const float* conn_i = (const float*)d_in[2];
    const float* ph     = (const float*)d_in[3];
    const float* sg     = (const float*)d_in[4];
    const float* rw     = (const float*)d_in[5];
    const float* rb     = (const float*)d_in[6];
    const int*   nsp    = (const int*)d_in[7];
    const int*   injp   = (const int*)d_in[8];

    cudaFuncSetAttribute(k_step, cudaFuncAttributeMaxDynamicSharedMemorySize, SMEM_BYTES);

    k_init<<<1, 32>>>();
    const int n_img = BATCH * 28 * 28;
    k_absmax<<<(n_img + 511) / 512, 512>>>(images, n_img);
    k_prepS<<<(KDIM * NDIM + 255) / 256, 256>>>(conn_r, conn_i, ph, sg);
    k_pinj<<<(BATCH * NM * NV1 + 255) / 256, 256>>>(images);

    for (int t = 0; t < 10; t++)
        k_step<<<GRID, TPB, SMEM_BYTES>>>(t, nsp, injp);

    k_final<<<BATCH, 320>>>(rw, rb, (float*)d_out);
}

// round 9
// speedup vs baseline: 1.7679x; 1.1074x over previous
#include <cuda_runtime.h>
#include <cuda_bf16.h>
#include <math.h>

// ---------------- problem constants ----------------
#define N_SW   131
#define NLC    33                 // distinct |L-32| classes
#define NM     16                 // only m<16 nonzero
#define BATCH  128
#define NV1    49
#define ROWS   (BATCH*NLC*NM)     // 67584

// ---------------- GEMM formulation ----------------
#define KHALF  144
#define KDIM   288
#define NDIM   136
#define SSTRIDE_B 272
#define ASTRIDE_B 592
#define CHUNK  64
#define NCHUNK (ROWS/CHUNK)       // 1056
#define GRID   148
#define TPB    256

#define S_BYTES  (KDIM*NDIM*2)    // 78336
#define S_HI_OFF 0
#define S_LO_OFF S_BYTES
#define A_HI_OFF (2*S_BYTES)
#define A_BYTES  (CHUNK*ASTRIDE_B)
#define A_LO_OFF (A_HI_OFF + A_BYTES)
#define SMEM_BYTES (A_LO_OFF + A_BYTES)   // 232448
#define G_OFF    A_HI_OFF
#define GSTRIDE  288

// ---------------- persistent device scratch ----------------
__device__ float2 g_field[(size_t)ROWS * N_SW];
__device__ __align__(16) __nv_bfloat16 g_S_hi[KDIM * NDIM];
__device__ __align__(16) __nv_bfloat16 g_S_lo[KDIM * NDIM];
__device__ float  g_gain[N_SW];
__device__ float  g_pinj[BATCH * NM * NV1];
__device__ float  g_erow[10 * ROWS];
__device__ int    g_absmax_bits;

// ---------------- helpers ----------------
__device__ __forceinline__ unsigned smem_addr(const void* p) {
    unsigned a;
    asm("{ .reg .u64 t; cvta.to.shared.u64 t, %1; cvt.u32.u64 %0, t; }" : "=r"(a) : "l"(p));
    return a;
}
#define LDSM4(R, addr) \
    asm volatile("ldmatrix.sync.aligned.m8n8.x4.shared.b16 {%0,%1,%2,%3}, [%4];" \
        : "=r"((R)[0]), "=r"((R)[1]), "=r"((R)[2]), "=r"((R)[3]) : "r"(addr))
#define LDSM2T(R, addr) \
    asm volatile("ldmatrix.sync.aligned.m8n8.x2.trans.shared.b16 {%0,%1}, [%2];" \
        : "=r"((R)[0]), "=r"((R)[1]) : "r"(addr))
#define MMA_BF16(C, A, B) \
    asm volatile("mma.sync.aligned.m16n8k16.row.col.f32.bf16.bf16.f32 " \
        "{%0,%1,%2,%3}, {%4,%5,%6,%7}, {%8,%9}, {%0,%1,%2,%3};" \
        : "+f"((C)[0]), "+f"((C)[1]), "+f"((C)[2]), "+f"((C)[3]) \
        : "r"((A)[0]), "r"((A)[1]), "r"((A)[2]), "r"((A)[3]), "r"((B)[0]), "r"((B)[1]))

// MUFU.TANH: single-instruction tanh (sm_75+), rel err ~2^-11
__device__ __forceinline__ float tanh_fast(float x) {
    float r;
    asm("tanh.approx.f32 %0, %1;" : "=f"(r) : "f"(x));
    return r;
}

// out = f * tanh(|f|*g)/|f| ; 2 MUFU (rsqrt + tanh) + ~7 FMA
__device__ __forceinline__ void outfun(float fr, float fi, float g,
                                       float& orr, float& oii) {
    float sq  = fmaf(fr, fr, fmaf(fi, fi, 1e-8f));
    float inv = rsqrtf(sq);                 // MUFU.RSQ ; 1/mag
    float x   = (g * sq) * inv;             // g * mag
    float sc  = tanh_fast(x) * inv;         // tanh(g*mag)/mag
    orr = fr * sc;
    oii = fi * sc;
}

// hi = truncate-to-bf16 (exact bits), lo = bf16(v - hi); residual split
__device__ __forceinline__ void store_split(unsigned short* ah, unsigned short* al,
                                            int idx, float v) {
    unsigned bits = __float_as_uint(v);
    unsigned short h = (unsigned short)(bits >> 16);
    float hf = __uint_as_float(bits & 0xFFFF0000u);
    ah[idx] = h;
    al[idx] = __bfloat16_as_ushort(__float2bfloat16(v - hf));
}

// ---------------- prep kernels ----------------
__global__ void k_init() { if (threadIdx.x == 0) g_absmax_bits = 0; }

__global__ void k_absmax(const float* __restrict__ img, int n) {
    int i = blockIdx.x * blockDim.x + threadIdx.x;
    float v = (i < n) ? fabsf(img[i]) : 0.f;
    #pragma unroll
    for (int o = 16; o > 0; o >>= 1) v = fmaxf(v, __shfl_xor_sync(0xffffffffu, v, o));
    if ((threadIdx.x & 31) == 0) atomicMax(&g_absmax_bits, __float_as_int(v));
}

__global__ void k_prepS(const float* __restrict__ cr, const float* __restrict__ ci,
                        const float* __restrict__ ph, const float* __restrict__ sg) {
    int i = blockIdx.x * blockDim.x + threadIdx.x;
    if (i < KDIM * NDIM) {
        int k = i / NDIM, t = i % NDIM;
        float val = 0.f;
        if (t < N_SW) {
            float sp, cp;
            sincosf(ph[t], &sp, &cp);
            if (k < N_SW) {
                float a = cr[k * N_SW + t], b = ci[k * N_SW + t];
                val = a * cp - b * sp;                       // C_r
            } else if (k >= KHALF && k < KHALF + N_SW) {
                int s = k - KHALF;
                float a = cr[s * N_SW + t], b = ci[s * N_SW + t];
                val = -(a * sp + b * cp);                    // -C_i
            }
        }
        __nv_bfloat16 h = __float2bfloat16(val);
        float hf = __bfloat162float(h);
        g_S_hi[i] = h;
        g_S_lo[i] = __float2bfloat16(val - hf);
    }
    if (i < N_SW) {
        float x = sg[i];
        g_gain[i] = fmaxf(x, 0.f) + log1pf(expf(-fabsf(x)));
    }
}

__global__ void k_pinj(const float* __restrict__ img) {
    int i = blockIdx.x * blockDim.x + threadIdx.x;
    if (i >= BATCH * NM * NV1) return;
    int b   = i / (NM * NV1);
    int rem = i - b * (NM * NV1);
    int m   = rem / NV1;
    int s   = rem - m * NV1;
    int pr = s / 7, pc = s - pr * 7;
    int ir = m >> 2, ic = m & 3;
    float am   = __int_as_float(g_absmax_bits);
    float coef = (am > 1e-8f) ? 0.3f / am : 0.3f;
    g_pinj[i] = coef * img[b * 784 + (pr * 4 + ir) * 28 + (pc * 4 + ic)];
}

// ---------------- main recurrence step ----------------
__global__ __launch_bounds__(TPB, 1) void k_step(int step,
                                                 const int* __restrict__ nsp,
                                                 const int* __restrict__ injp) {
    extern __shared__ unsigned char smem[];
    const int ns = *nsp;
    if (step >= ns) return;
    const int injs = *injp;
    const bool inject = (step < injs);
    const bool last   = (step == ns - 1);

    {
        const uint4* sh = (const uint4*)g_S_hi;
        const uint4* sl = (const uint4*)g_S_lo;
        uint4* dh = (uint4*)(smem + S_HI_OFF);
        uint4* dl = (uint4*)(smem + S_LO_OFF);
        for (int i = threadIdx.x; i < S_BYTES / 16; i += TPB) { dh[i] = sh[i]; dl[i] = sl[i]; }
    }
    const int warp = threadIdx.x >> 5;
    const int lane = threadIdx.x & 31;
    const int mtp    = warp >> 2;
    const int nlane4 = warp & 3;

    float gain_reg[5];
    #pragma unroll
    for (int j = 0; j < 5; j++) {
        int t = lane + 32 * j;
        gain_reg[j] = (t < N_SW) ? g_gain[t] : 0.f;
    }
    __syncthreads();

    const unsigned smem_base = smem_addr(smem);

    for (int chunk = blockIdx.x; chunk < NCHUNK; chunk += GRID) {
        const int rowBase = chunk * CHUNK;

        if (step > 0) {
            // ---- Phase A: out -> A hi/lo bf16 smem (2 MUFU per value) ----
            for (int r = 0; r < 8; r++) {
                int lrow = warp * 8 + r;
                const float2* f = g_field + (size_t)(rowBase + lrow) * N_SW;
                unsigned short* ah = (unsigned short*)(smem + A_HI_OFF + lrow * ASTRIDE_B);
                unsigned short* al = (unsigned short*)(smem + A_LO_OFF + lrow * ASTRIDE_B);
                #pragma unroll
                for (int j = 0; j < 5; j++) {
                    int t = lane + 32 * j;
                    if (t < KHALF) {
                        float orr = 0.f, oii = 0.f;
                        if (t < N_SW) {
                            float2 fv = f[t];
                            outfun(fv.x, fv.y, gain_reg[j], orr, oii);
                        }
                        store_split(ah, al, t, orr);
                        store_split(ah, al, KHALF + t, oii);
                    }
                }
            }
            __syncthreads();

            // ---- Phase B: bf16-split mma, 3 passes (HH + HL + LH) ----
            float acc[18][4];
            #pragma unroll
            for (int i = 0; i < 18; i++)
                #pragma unroll
                for (int c = 0; c < 4; c++) acc[i][c] = 0.f;

            for (int kt = 0; kt < 18; kt++) {
                unsigned aH[2][4], aL[2][4];
                #pragma unroll
                for (int mi = 0; mi < 2; mi++) {
                    int mta = 2 * mtp + mi;
                    unsigned arow = (lane & 15) + 16 * mta;
                    unsigned acol = 16 * kt + ((lane >> 4) << 3);
                    unsigned addrH = smem_base + A_HI_OFF + arow * ASTRIDE_B + acol * 2;
                    LDSM4(aH[mi], addrH);
                    LDSM4(aL[mi], addrH + (unsigned)A_BYTES);
                }
                #pragma unroll
                for (int q = 0; q < 9; q++) {
                    int ntG = nlane4 + 4 * q;
                    if (ntG > 33) ntG = 33;
                    int G  = (ntG >= 17) ? 1 : 0;
                    int nt = ntG - 17 * G;
                    int kts = G ? ((kt < 9) ? kt + 9 : kt - 9) : kt;
                    bool neg = (G && kt < 9);
                    unsigned baddr = smem_base + S_HI_OFF
                                   + (16 * kts + (lane & 15)) * SSTRIDE_B + nt * 16;
                    unsigned bh[2], bl[2];
                    LDSM2T(bh, baddr);
                    LDSM2T(bl, baddr + (unsigned)S_BYTES);
                    if (neg) {
                        bh[0] ^= 0x80008000u; bh[1] ^= 0x80008000u;
                        bl[0] ^= 0x80008000u; bl[1] ^= 0x80008000u;
                    }
                    #pragma unroll
                    for (int mi = 0; mi < 2; mi++) {
                        MMA_BF16(acc[q * 2 + mi], aH[mi], bh);
                        MMA_BF16(acc[q * 2 + mi], aH[mi], bl);
                        MMA_BF16(acc[q * 2 + mi], aL[mi], bh);
                    }
                }
            }
            __syncthreads();

            float* gsm = (float*)(smem + G_OFF);
            #pragma unroll
            for (int q = 0; q < 9; q++) {
                int ntG = nlane4 + 4 * q;
                if (ntG > 33) ntG = 33;
                int G  = (ntG >= 17) ? 1 : 0;
                int nt = ntG - 17 * G;
                int colBase = G * KHALF + nt * 8 + (lane & 3) * 2;
                #pragma unroll
                for (int mi = 0; mi < 2; mi++) {
                    int row0 = 16 * (2 * mtp + mi) + (lane >> 2);
                    float* a = acc[q * 2 + mi];
                    *(float2*)&gsm[row0 * GSTRIDE + colBase]       = make_float2(a[0], a[1]);
                    *(float2*)&gsm[(row0 + 8) * GSTRIDE + colBase] = make_float2(a[2], a[3]);
                }
            }
            __syncthreads();
        }

        // ---- Phase C: field update; last step -> energy ----
        {
            const float* gsm = (const float*)(smem + G_OFF);
            for (int r = 0; r < 8; r++) {
                int lrow = warp * 8 + r;
                int grow = rowBase + lrow;
                int b    = grow / (NLC * NM);
                int rem  = grow - b * (NLC * NM);
                int lc   = rem >> 4;
                int m    = rem & 15;
                float w    = 1.0f - (float)lc * 0.015625f;
                float mult = (lc == 0 || lc == NLC - 1) ? 1.0f : 2.0f;
                float2* f = g_field + (size_t)grow * N_SW;
                const float* pj = g_pinj + (b * NM + m) * NV1;
                #pragma unroll
                for (int j = 0; j < 5; j++) {
                    int t = lane + 32 * j;
                    if (t < N_SW) {
                        float fr = 0.f, fi = 0.f;
                        if (step > 0) { float2 fv = f[t]; fr = fv.x; fi = fv.y; }
                        if (inject && t < NV1) fr += pj[t] * w;
                        float gr = 0.f, gi = 0.f;
                        if (step > 0) {
                            gr = gsm[lrow * GSTRIDE + t];
                            gi = gsm[lrow * GSTRIDE + KHALF + t];
                        }
                        fr = fr * 0.85f + gr * 0.25f;
                        fi = fi * 0.85f + gi * 0.25f;
                        f[t] = make_float2(fr, fi);
                        if (last && t >= 121) {
                            float orr, oii;
                            outfun(fr, fi, gain_reg[j], orr, oii);
                            g_erow[(t - 121) * ROWS + grow] = mult * (orr * orr + oii * oii);
                        }
                    }
                }
            }
        }
        if (step > 0) __syncthreads();
    }
}

// ---------------- readout ----------------
__global__ void k_final(const float* __restrict__ rw, const float* __restrict__ rb,
                        float* __restrict__ out) {
    __shared__ float feat[10];
    int b = blockIdx.x;
    int warp = threadIdx.x >> 5, lane = threadIdx.x & 31;
    if (warp < 10) {
        float s = 0.f;
        const float* e = g_erow + warp * ROWS + b * (NLC * NM);
        for (int k = lane; k < NLC * NM; k += 32) s += e[k];
        #pragma unroll
        for (int o = 16; o > 0; o >>= 1) s += __shfl_xor_sync(0xffffffffu, s, o);
        if (lane == 0) feat[warp] = log1pf(s + 1e-8f);
    }
    __syncthreads();
    if (threadIdx.x < 10) {
        int c = threadIdx.x;
        float acc = rb[c];
        #pragma unroll
        for (int o = 0; o < 10; o++) acc += feat[o] * rw[c * 10 + o];
        out[b * 10 + c] = acc;
    }
}

// ---------------- entry ----------------
extern "C" void kernel_launch(void* const* d_in, const int* in_sizes, int n_in,
                              void* d_out, int out_size) {
    const float* images = (const float*)d_in[0];
    const float* conn_r = (const float*)d_in[1];
    const float* conn_i = (const float*)d_in[2];
    const float* ph     = (const float*)d_in[3];
    const float* sg     = (const float*)d_in[4];
    const float* rw     = (const float*)d_in[5];
    const float* rb     = (const float*)d_in[6];
    const int*   nsp    = (const int*)d_in[7];
    const int*   injp   = (const int*)d_in[8];

    cudaFuncSetAttribute(k_step, cudaFuncAttributeMaxDynamicSharedMemorySize, SMEM_BYTES);

    k_init<<<1, 32>>>();
    const int n_img = BATCH * 28 * 28;
    k_absmax<<<(n_img + 511) / 512, 512>>>(images, n_img);
    k_prepS<<<(KDIM * NDIM + 255) / 256, 256>>>(conn_r, conn_i, ph, sg);
    k_pinj<<<(BATCH * NM * NV1 + 255) / 256, 256>>>(images);

    for (int t = 0; t < 10; t++)
        k_step<<<GRID, TPB, SMEM_BYTES>>>(t, nsp, injp);

    k_final<<<BATCH, 320>>>(rw, rb, (float*)d_out);
}

// round 11
// speedup vs baseline: 2.0926x; 1.1837x over previous
#include <cuda_runtime.h>
#include <cuda_bf16.h>
#include <math.h>

// ---------------- problem constants ----------------
#define N_SW   131
#define NLC    33                 // distinct |L-32| classes
#define NM     16                 // only m<16 nonzero
#define BATCH  128
#define NV1    49
#define ROWS   (BATCH*NLC*NM)     // 67584

// ---------------- GEMM formulation ----------------
// A[row][k], k in [0,288): k<144 -> O_r (s=k, valid s<131), k>=144 -> O_i (s=k-144)
// S[k][t] (288 x 136): k<131 -> C_r[k][t]; 144<=k<275 -> -C_i[k-144][t]; else 0
// G_r = A*S ; G_i = A*B_i with B_i(k-tile kt) = (kt<9 ? -S[kt+9] : S[kt-9])
// A is single bf16 (RN); S is hi/lo split -> 2 MMA passes (Ah*Sh + Ah*Sl)
#define KHALF  144
#define KDIM   288
#define NDIM   136
#define SSTRIDE_B 272             // 17*16 -> ldsm-aligned
#define ASTRIDE_B 592             // 37*16 -> ldsm-aligned, conflict-free
#define CHUNK  64
#define NCHUNK (ROWS/CHUNK)       // 1056
#define GRID   148
#define TPB    256

#define S_BYTES  (KDIM*NDIM*2)    // 78336
#define S_HI_OFF 0
#define S_LO_OFF S_BYTES
#define A_HI_OFF (2*S_BYTES)      // 156672 (A overlays the G region)
#define G_OFF    (2*S_BYTES)
#define G_BYTES  (CHUNK*KDIM*4)   // 73728
#define SMEM_BYTES (G_OFF + G_BYTES)   // 230400 <= 232448
#define GSTRIDE  288

// ---------------- persistent device scratch ----------------
__device__ float2 g_field[(size_t)ROWS * N_SW];
__device__ __align__(16) __nv_bfloat16 g_S_hi[KDIM * NDIM];
__device__ __align__(16) __nv_bfloat16 g_S_lo[KDIM * NDIM];
__device__ float  g_gain[N_SW];
__device__ float  g_pinj[BATCH * NM * NV1];
__device__ float  g_erow[10 * ROWS];
__device__ int    g_absmax_bits;

// ---------------- helpers ----------------
__device__ __forceinline__ unsigned smem_addr(const void* p) {
    unsigned a;
    asm("{ .reg .u64 t; cvta.to.shared.u64 t, %1; cvt.u32.u64 %0, t; }" : "=r"(a) : "l"(p));
    return a;
}
#define LDSM4(R, addr) \
    asm volatile("ldmatrix.sync.aligned.m8n8.x4.shared.b16 {%0,%1,%2,%3}, [%4];" \
        : "=r"((R)[0]), "=r"((R)[1]), "=r"((R)[2]), "=r"((R)[3]) : "r"(addr))
#define LDSM2T(R, addr) \
    asm volatile("ldmatrix.sync.aligned.m8n8.x2.trans.shared.b16 {%0,%1}, [%2];" \
        : "=r"((R)[0]), "=r"((R)[1]) : "r"(addr))
#define MMA_BF16(C, A, B) \
    asm volatile("mma.sync.aligned.m16n8k16.row.col.f32.bf16.bf16.f32 " \
        "{%0,%1,%2,%3}, {%4,%5,%6,%7}, {%8,%9}, {%0,%1,%2,%3};" \
        : "+f"((C)[0]), "+f"((C)[1]), "+f"((C)[2]), "+f"((C)[3]) \
        : "r"((A)[0]), "r"((A)[1]), "r"((A)[2]), "r"((A)[3]), "r"((B)[0]), "r"((B)[1]))

// MUFU.TANH: single-instruction tanh (sm_75+), rel err ~2^-11
__device__ __forceinline__ float tanh_fast(float x) {
    float r;
    asm("tanh.approx.f32 %0, %1;" : "=f"(r) : "f"(x));
    return r;
}

// out = f * tanh(|f|*g)/|f| ; 2 MUFU (rsqrt + tanh)
__device__ __forceinline__ void outfun(float fr, float fi, float g,
                                       float& orr, float& oii) {
    float sq  = fmaf(fr, fr, fmaf(fi, fi, 1e-8f));
    float inv = rsqrtf(sq);
    float sc  = tanh_fast(g * sq * inv) * inv;
    orr = fr * sc;
    oii = fi * sc;
}

// ---------------- prep kernels ----------------
__global__ void k_init() { if (threadIdx.x == 0) g_absmax_bits = 0; }

__global__ void k_absmax(const float* __restrict__ img, int n) {
    int i = blockIdx.x * blockDim.x + threadIdx.x;
    float v = (i < n) ? fabsf(img[i]) : 0.f;
    #pragma unroll
    for (int o = 16; o > 0; o >>= 1) v = fmaxf(v, __shfl_xor_sync(0xffffffffu, v, o));
    if ((threadIdx.x & 31) == 0) atomicMax(&g_absmax_bits, __float_as_int(v));
}

__global__ void k_prepS(const float* __restrict__ cr, const float* __restrict__ ci,
                        const float* __restrict__ ph, const float* __restrict__ sg) {
    int i = blockIdx.x * blockDim.x + threadIdx.x;
    if (i < KDIM * NDIM) {
        int k = i / NDIM, t = i % NDIM;
        float val = 0.f;
        if (t < N_SW) {
            float sp, cp;
            sincosf(ph[t], &sp, &cp);
            if (k < N_SW) {
                float a = cr[k * N_SW + t], b = ci[k * N_SW + t];
                val = a * cp - b * sp;                       // C_r
            } else if (k >= KHALF && k < KHALF + N_SW) {
                int s = k - KHALF;
                float a = cr[s * N_SW + t], b = ci[s * N_SW + t];
                val = -(a * sp + b * cp);                    // -C_i
            }
        }
        __nv_bfloat16 h = __float2bfloat16(val);
        float hf = __bfloat162float(h);
        g_S_hi[i] = h;
        g_S_lo[i] = __float2bfloat16(val - hf);
    }
    if (i < N_SW) {
        float x = sg[i];
        g_gain[i] = fmaxf(x, 0.f) + log1pf(expf(-fabsf(x)));
    }
}

__global__ void k_pinj(const float* __restrict__ img) {
    int i = blockIdx.x * blockDim.x + threadIdx.x;
    if (i >= BATCH * NM * NV1) return;
    int b   = i / (NM * NV1);
    int rem = i - b * (NM * NV1);
    int m   = rem / NV1;
    int s   = rem - m * NV1;
    int pr = s / 7, pc = s - pr * 7;
    int ir = m >> 2, ic = m & 3;
    float am   = __int_as_float(g_absmax_bits);
    float coef = (am > 1e-8f) ? 0.3f / am : 0.3f;
    g_pinj[i] = coef * img[b * 784 + (pr * 4 + ir) * 28 + (pc * 4 + ic)];
}

// ---------------- main recurrence step ----------------
__global__ __launch_bounds__(TPB, 1) void k_step(int step,
                                                 const int* __restrict__ nsp,
                                                 const int* __restrict__ injp) {
    extern __shared__ unsigned char smem[];
    const int ns = *nsp;
    if (step >= ns) return;
    const int injs = *injp;
    const bool inject = (step < injs);
    const bool last   = (step == ns - 1);
    // step 1: A nonzero only for k<64 (O_r t<49; O_i==0) -> only 4 K-tiles
    const int ktmax = (step == 1) ? 4 : 18;

    {
        const uint4* sh = (const uint4*)g_S_hi;
        const uint4* sl = (const uint4*)g_S_lo;
        uint4* dh = (uint4*)(smem + S_HI_OFF);
        uint4* dl = (uint4*)(smem + S_LO_OFF);
        for (int i = threadIdx.x; i < S_BYTES / 16; i += TPB) { dh[i] = sh[i]; dl[i] = sl[i]; }
    }
    const int warp = threadIdx.x >> 5;
    const int lane = threadIdx.x & 31;
    const int mtp    = warp >> 2;
    const int nlane4 = warp & 3;

    float gain_reg[5];
    #pragma unroll
    for (int j = 0; j < 5; j++) {
        int t = lane + 32 * j;
        gain_reg[j] = (t < N_SW) ? g_gain[t] : 0.f;
    }
    __syncthreads();

    const unsigned smem_base = smem_addr(smem);

    for (int chunk = blockIdx.x; chunk < NCHUNK; chunk += GRID) {
        const int rowBase = chunk * CHUNK;

        if (step > 0) {
            // ---- Phase A: out -> A bf16 (RN) smem ----
            for (int r = 0; r < 8; r++) {
                int lrow = warp * 8 + r;
                const float2* f = g_field + (size_t)(rowBase + lrow) * N_SW;
                unsigned short* ah = (unsigned short*)(smem + A_HI_OFF + lrow * ASTRIDE_B);
                #pragma unroll
                for (int j = 0; j < 5; j++) {
                    int t = lane + 32 * j;
                    if (t < KHALF) {
                        float orr = 0.f, oii = 0.f;
                        if (t < N_SW) {
                            float2 fv = f[t];
                            outfun(fv.x, fv.y, gain_reg[j], orr, oii);
                        }
                        ah[t]         = __bfloat16_as_ushort(__float2bfloat16(orr));
                        ah[KHALF + t] = __bfloat16_as_ushort(__float2bfloat16(oii));
                    }
                }
            }
            __syncthreads();

            // ---- Phase B: 2-pass mma (Ah*Sh + Ah*Sl) ----
            float acc[18][4];
            #pragma unroll
            for (int i = 0; i < 18; i++)
                #pragma unroll
                for (int c = 0; c < 4; c++) acc[i][c] = 0.f;

            for (int kt = 0; kt < ktmax; kt++) {
                unsigned aH[2][4];
                #pragma unroll
                for (int mi = 0; mi < 2; mi++) {
                    int mta = 2 * mtp + mi;
                    unsigned arow = (lane & 15) + 16 * mta;
                    unsigned acol = 16 * kt + ((lane >> 4) << 3);
                    LDSM4(aH[mi], smem_base + A_HI_OFF + arow * ASTRIDE_B + acol * 2);
                }
                #pragma unroll
                for (int q = 0; q < 9; q++) {
                    int ntG = nlane4 + 4 * q;
                    if (ntG > 33) ntG = 33;
                    int G  = (ntG >= 17) ? 1 : 0;
                    int nt = ntG - 17 * G;
                    int kts = G ? ((kt < 9) ? kt + 9 : kt - 9) : kt;
                    bool neg = (G && kt < 9);
                    unsigned baddr = smem_base + S_HI_OFF
                                   + (16 * kts + (lane & 15)) * SSTRIDE_B + nt * 16;
                    unsigned bh[2], bl[2];
                    LDSM2T(bh, baddr);
                    LDSM2T(bl, baddr + (unsigned)S_BYTES);
                    if (neg) {
                        bh[0] ^= 0x80008000u; bh[1] ^= 0x80008000u;
                        bl[0] ^= 0x80008000u; bl[1] ^= 0x80008000u;
                    }
                    #pragma unroll
                    for (int mi = 0; mi < 2; mi++) {
                        MMA_BF16(acc[q * 2 + mi], aH[mi], bh);
                        MMA_BF16(acc[q * 2 + mi], aH[mi], bl);
                    }
                }
            }
            __syncthreads();

            float* gsm = (float*)(smem + G_OFF);
            #pragma unroll
            for (int q = 0; q < 9; q++) {
                int ntG = nlane4 + 4 * q;
                if (ntG > 33) ntG = 33;
                int G  = (ntG >= 17) ? 1 : 0;
                int nt = ntG - 17 * G;
                int colBase = G * KHALF + nt * 8 + (lane & 3) * 2;
                #pragma unroll
                for (int mi = 0; mi < 2; mi++) {
                    int row0 = 16 * (2 * mtp + mi) + (lane >> 2);
                    float* a = acc[q * 2 + mi];
                    *(float2*)&gsm[row0 * GSTRIDE + colBase]       = make_float2(a[0], a[1]);
                    *(float2*)&gsm[(row0 + 8) * GSTRIDE + colBase] = make_float2(a[2], a[3]);
                }
            }
            __syncthreads();
        }

        // ---- Phase C: field update; last step -> energy ----
        {
            const float* gsm = (const float*)(smem + G_OFF);
            for (int r = 0; r < 8; r++) {
                int lrow = warp * 8 + r;
                int grow = rowBase + lrow;
                int b    = grow / (NLC * NM);
                int rem  = grow - b * (NLC * NM);
                int lc   = rem >> 4;
                int m    = rem & 15;
                float w    = 1.0f - (float)lc * 0.015625f;
                float mult = (lc == 0 || lc == NLC - 1) ? 1.0f : 2.0f;
                float2* f = g_field + (size_t)grow * N_SW;
                const float* pj = g_pinj + (b * NM + m) * NV1;
                #pragma unroll
                for (int j = 0; j < 5; j++) {
                    int t = lane + 32 * j;
                    if (t < N_SW) {
                        float fr = 0.f, fi = 0.f;
                        if (step > 0) { float2 fv = f[t]; fr = fv.x; fi = fv.y; }
                        if (inject && t < NV1) fr += pj[t] * w;
                        float gr = 0.f, gi = 0.f;
                        if (step > 0) {
                            gr = gsm[lrow * GSTRIDE + t];
                            gi = gsm[lrow * GSTRIDE + KHALF + t];
                        }
                        fr = fr * 0.85f + gr * 0.25f;
                        fi = fi * 0.85f + gi * 0.25f;
                        f[t] = make_float2(fr, fi);
                        if (last && t >= 121) {
                            float orr, oii;
                            outfun(fr, fi, gain_reg[j], orr, oii);
                            g_erow[(t - 121) * ROWS + grow] = mult * (orr * orr + oii * oii);
                        }
                    }
                }
            }
        }
        if (step > 0) __syncthreads();
    }
}

// ---------------- readout ----------------
__global__ void k_final(const float* __restrict__ rw, const float* __restrict__ rb,
                        float* __restrict__ out) {
    __shared__ float feat[10];
    int b = blockIdx.x;
    int warp = threadIdx.x >> 5, lane = threadIdx.x & 31;
    if (warp < 10) {
        float s = 0.f;
        const float* e = g_erow + warp * ROWS + b * (NLC * NM);
        for (int k = lane; k < NLC * NM; k += 32) s += e[k];
        #pragma unroll
        for (int o = 16; o > 0; o >>= 1) s += __shfl_xor_sync(0xffffffffu, s, o);
        if (lane == 0) feat[warp] = log1pf(s + 1e-8f);
    }
    __syncthreads();
    if (threadIdx.x < 10) {
        int c = threadIdx.x;
        float acc = rb[c];
        #pragma unroll
        for (int o = 0; o < 10; o++) acc += feat[o] * rw[c * 10 + o];
        out[b * 10 + c] = acc;
    }
}

// ---------------- entry ----------------
extern "C" void kernel_launch(void* const* d_in, const int* in_sizes, int n_in,
                              void* d_out, int out_size) {
    const float* images = (const float*)d_in[0];
    const float* conn_r = (const float*)d_in[1];
    const float* conn_i = (const float*)d_in[2];
    const float* ph     = (const float*)d_in[3];
    const float* sg     = (const float*)d_in[4];
    const float* rw     = (const float*)d_in[5];
    const float* rb     = (const float*)d_in[6];
    const int*   nsp    = (const int*)d_in[7];
    const int*   injp   = (const int*)d_in[8];

    cudaFuncSetAttribute(k_step, cudaFuncAttributeMaxDynamicSharedMemorySize, SMEM_BYTES);

    k_init<<<1, 32>>>();
    const int n_img = BATCH * 28 * 28;
    k_absmax<<<(n_img + 511) / 512, 512>>>(images, n_img);
    k_prepS<<<(KDIM * NDIM + 255) / 256, 256>>>(conn_r, conn_i, ph, sg);
    k_pinj<<<(BATCH * NM * NV1 + 255) / 256, 256>>>(images);

    for (int t = 0; t < 10; t++)
        k_step<<<GRID, TPB, SMEM_BYTES>>>(t, nsp, injp);

    k_final<<<BATCH, 320>>>(rw, rb, (float*)d_out);
}